// round 1
// baseline (speedup 1.0000x reference)
#include <cuda_runtime.h>
#include <math.h>

// ---------------- problem constants ----------------
#define Bb   32
#define SEQ  512
#define EE   128
#define HH   8
#define EHH  1024
#define LL   3
#define TOK  (Bb*SEQ)      // 16384 tokens
#define BHH  (Bb*HH)       // 256 (b,h) pairs
#define KF   101
#define ADIM 200

// ---------------- device scratch (statics: allowed) ----------------
__device__ float g_x    [(size_t)TOK*EE];
__device__ float g_xinit[(size_t)TOK*EE];
__device__ float g_xn   [(size_t)TOK*EE];
__device__ float g_q    [(size_t)BHH*SEQ*EE];
__device__ float g_k    [(size_t)BHH*SEQ*EE];
__device__ float g_v    [(size_t)BHH*SEQ*EE];
__device__ float g_S    [(size_t)BHH*SEQ*SEQ];   // 268 MB logits/attn
__device__ float g_vals [(size_t)TOK*EHH];
__device__ float g_o    [(size_t)TOK*EHH];
__device__ float g_out1 [(size_t)TOK*EE];
__device__ float g_out2 [(size_t)TOK*EE];
__device__ float g_w    [TOK];

// ---------------- helpers ----------------
__device__ __forceinline__ float blkSum128(float v, float* sm) {
    #pragma unroll
    for (int o = 16; o > 0; o >>= 1) v += __shfl_xor_sync(0xffffffffu, v, o);
    int w = threadIdx.x >> 5;
    if ((threadIdx.x & 31) == 0) sm[w] = v;
    __syncthreads();
    float r = sm[0] + sm[1] + sm[2] + sm[3];
    __syncthreads();
    return r;
}

// ---------------- embed: x = atom_table[idx]@comp_W + comp_b + str@pdd_W + pdd_b ----------------
__global__ void embed_kernel(const float* __restrict__ str_fea,
                             const int*   __restrict__ comp_fea,
                             const float* __restrict__ atom_table,
                             const float* __restrict__ comp_W,
                             const float* __restrict__ comp_b,
                             const float* __restrict__ pdd_W,
                             const float* __restrict__ pdd_b) {
    int t = blockIdx.x;
    int e = threadIdx.x;              // 0..127
    __shared__ float sa[ADIM];
    __shared__ float ss[KF-1];
    const float* sf = str_fea + (size_t)t*KF;
    int idx = comp_fea[t];
    const float* at = atom_table + (size_t)idx*ADIM;
    for (int j = e; j < ADIM; j += EE) sa[j] = at[j];
    for (int j = e; j < KF-1; j += EE) ss[j] = sf[1+j];
    if (e == 0) g_w[t] = sf[0];
    __syncthreads();
    float acc = comp_b[e] + pdd_b[e];
    #pragma unroll 4
    for (int a = 0; a < ADIM; a++) acc = fmaf(sa[a], comp_W[a*EE + e], acc);
    #pragma unroll 4
    for (int j = 0; j < KF-1; j++) acc = fmaf(ss[j], pdd_W[j*EE + e], acc);
    g_x[(size_t)t*EE + e]     = acc;
    g_xinit[(size_t)t*EE + e] = acc;
}

// ---------------- layernorm over E=128 (optionally sum of two inputs) ----------------
__global__ void ln_kernel(const float* __restrict__ src1,
                          const float* __restrict__ src2,
                          const float* __restrict__ gam,
                          const float* __restrict__ bet,
                          float* __restrict__ dst) {
    __shared__ float sm[4];
    int t = blockIdx.x, e = threadIdx.x;
    size_t off = (size_t)t*EE + e;
    float v = src1[off];
    if (src2) v += src2[off];
    float m = blkSum128(v, sm) * (1.f/EE);
    float d = v - m;
    float var = blkSum128(d*d, sm) * (1.f/EE);
    dst[off] = d * rsqrtf(var + 1e-5f) * gam[e] + bet[e];
}

// ---------------- generic tiled fp32 GEMM with epilogues ----------------
#define BM 64
#define BN 64
#define BK 16

enum { EPI_BIAS=0, EPI_BIAS_ADD=1, EPI_MISH=2, EPI_QKV=3, EPI_LOGITS=4, EPI_VALS=5 };

template<int TB, int EPI>
__global__ __launch_bounds__(256)
void gemm_kernel(const float* __restrict__ A, int lda, size_t sA,
                 const float* __restrict__ B, int ldb, size_t sB,
                 float* __restrict__ C, int ldc, size_t sC,
                 int M, int Nn, int K,
                 const float* __restrict__ bias,
                 const float* __restrict__ addend) {
    int z = blockIdx.z;
    A += (size_t)z * sA;
    B += (size_t)z * sB;
    if (C) C += (size_t)z * sC;
    int bm = blockIdx.y * BM, bn = blockIdx.x * BN;

    __shared__ float As[BK][BM+4];
    __shared__ float Bs[BK][BN+4];

    int tid = threadIdx.x;
    int tx = tid & 15, ty = tid >> 4;
    float acc[4][4];
    #pragma unroll
    for (int i=0;i<4;i++)
        #pragma unroll
        for (int j=0;j<4;j++) acc[i][j]=0.f;

    for (int k0 = 0; k0 < K; k0 += BK) {
        #pragma unroll
        for (int i = tid; i < BM*BK; i += 256) {
            int r = i >> 4, c = i & 15;
            As[c][r] = A[(size_t)(bm + r)*lda + k0 + c];
        }
        if (TB == 0) {
            #pragma unroll
            for (int i = tid; i < BK*BN; i += 256) {
                int r = i >> 6, c = i & 63;
                Bs[r][c] = B[(size_t)(k0 + r)*ldb + bn + c];
            }
        } else {
            #pragma unroll
            for (int i = tid; i < BN*BK; i += 256) {
                int n = i >> 4, c = i & 15;
                Bs[c][n] = B[(size_t)(bn + n)*ldb + k0 + c];
            }
        }
        __syncthreads();
        #pragma unroll
        for (int kk = 0; kk < BK; kk++) {
            float a[4], bb[4];
            #pragma unroll
            for (int i=0;i<4;i++) a[i] = As[kk][ty*4+i];
            #pragma unroll
            for (int j=0;j<4;j++) bb[j] = Bs[kk][tx*4+j];
            #pragma unroll
            for (int i=0;i<4;i++)
                #pragma unroll
                for (int j=0;j<4;j++)
                    acc[i][j] = fmaf(a[i], bb[j], acc[i][j]);
        }
        __syncthreads();
    }

    #pragma unroll
    for (int i=0;i<4;i++) {
        int m = bm + ty*4 + i;
        #pragma unroll
        for (int j=0;j<4;j++) {
            int n = bn + tx*4 + j;
            float v = acc[i][j];
            if (EPI == EPI_BIAS) {
                C[(size_t)m*ldc + n] = v + bias[n];
            } else if (EPI == EPI_BIAS_ADD) {
                C[(size_t)m*ldc + n] = v + bias[n] + addend[(size_t)m*ldc + n];
            } else if (EPI == EPI_MISH) {
                float xv = v + bias[n];
                float sp = (xv > 20.f) ? xv : log1pf(expf(xv));
                C[(size_t)m*ldc + n] = xv * tanhf(sp);
            } else if (EPI == EPI_QKV) {
                float val = v + bias[n];
                int b = m >> 9, nn = m & 511;
                int h = n / 384, rem = n % 384;
                int r = rem >> 7, d = rem & 127;
                float* dst = (r == 0) ? g_q : (r == 1) ? g_k : g_v;
                dst[((size_t)(b*HH + h)*SEQ + nn)*EE + d] = val;
            } else if (EPI == EPI_LOGITS) {
                int b = z >> 3;
                bool mq = g_w[b*SEQ + m] > 0.f;
                bool mk = g_w[b*SEQ + n] > 0.f;
                C[(size_t)m*ldc + n] = (mq && mk) ? v * 0.08838834764831845f
                                                 : -9.0e15f;
            } else { // EPI_VALS
                int b = z >> 3, h = z & 7;
                g_vals[((size_t)(b*SEQ + m))*EHH + h*EE + n] = v;
            }
        }
    }
}

// ---------------- softmax with key-weight (w_attn) ----------------
__global__ void softmax_kernel() {
    // grid: (SEQ, BHH), 256 threads: each thread handles k=tid and k=tid+256
    int q  = blockIdx.x, bh = blockIdx.y;
    int b  = bh >> 3;
    float* row = g_S + ((size_t)bh*SEQ + q)*SEQ;
    int tid = threadIdx.x;
    __shared__ float sm[8];
    int w = tid >> 5, lane = tid & 31;

    float l0 = row[tid], l1 = row[tid + 256];
    float mx = fmaxf(l0, l1);
    #pragma unroll
    for (int o=16;o>0;o>>=1) mx = fmaxf(mx, __shfl_xor_sync(0xffffffffu, mx, o));
    if (lane==0) sm[w] = mx;
    __syncthreads();
    float m = sm[0];
    #pragma unroll
    for (int i=1;i<8;i++) m = fmaxf(m, sm[i]);
    __syncthreads();

    float w0 = g_w[b*SEQ + tid], w1 = g_w[b*SEQ + tid + 256];
    float e0 = w0 * expf(l0 - m);
    float e1 = w1 * expf(l1 - m);
    float s = e0 + e1;
    #pragma unroll
    for (int o=16;o>0;o>>=1) s += __shfl_xor_sync(0xffffffffu, s, o);
    if (lane==0) sm[w] = s;
    __syncthreads();
    float tot = sm[0];
    #pragma unroll
    for (int i=1;i<8;i++) tot += sm[i];

    float inv = 1.f / tot;
    row[tid]       = e0 * inv;
    row[tid + 256] = e1 * inv;
}

// ---------------- final: weighted pool + LN + head ----------------
__global__ void pool_head_kernel(const float* __restrict__ ln2_g,
                                 const float* __restrict__ ln2_b,
                                 const float* __restrict__ head_W,
                                 const float* __restrict__ head_b,
                                 float* __restrict__ out) {
    __shared__ float sm[4];
    int b = blockIdx.x, e = threadIdx.x;
    const float* xb  = g_x     + (size_t)b*SEQ*EE;
    const float* xib = g_xinit + (size_t)b*SEQ*EE;
    float s = 0.f;
    for (int n = 0; n < SEQ; n++)
        s = fmaf(g_w[b*SEQ + n], xb[n*EE + e] + xib[n*EE + e], s);
    float m = blkSum128(s, sm) * (1.f/EE);
    float d = s - m;
    float var = blkSum128(d*d, sm) * (1.f/EE);
    float p = d * rsqrtf(var + 1e-5f) * ln2_g[e] + ln2_b[e];
    float dot = blkSum128(p * head_W[e], sm);
    if (e == 0) out[b] = dot + head_b[0];
}

// ---------------- host launch ----------------
extern "C" void kernel_launch(void* const* d_in, const int* in_sizes, int n_in,
                              void* d_out, int out_size) {
    (void)in_sizes; (void)n_in; (void)out_size;
    const float* str_fea   = (const float*)d_in[0];
    const int*   comp_fea  = (const int*)  d_in[1];
    // d_in[2] = cell_fea: unused by reference
    const float* atom_table= (const float*)d_in[3];
    const float* comp_W    = (const float*)d_in[4];
    const float* comp_b    = (const float*)d_in[5];
    const float* pdd_W     = (const float*)d_in[6];
    const float* pdd_b     = (const float*)d_in[7];
    const float* enc_ln_g  = (const float*)d_in[8];
    const float* enc_ln_b  = (const float*)d_in[9];
    const float* qkv_W     = (const float*)d_in[10];
    const float* qkv_b     = (const float*)d_in[11];
    const float* o_W       = (const float*)d_in[12];
    const float* o_b       = (const float*)d_in[13];
    const float* out_W     = (const float*)d_in[14];
    const float* out_b     = (const float*)d_in[15];
    const float* ffn_W     = (const float*)d_in[16];
    const float* ffn_b     = (const float*)d_in[17];
    const float* ln2_g     = (const float*)d_in[18];
    const float* ln2_b     = (const float*)d_in[19];
    const float* head_W    = (const float*)d_in[20];
    const float* head_b    = (const float*)d_in[21];
    float* out = (float*)d_out;

    void* p;
    cudaGetSymbolAddress(&p, g_x);     float* px    = (float*)p;
    cudaGetSymbolAddress(&p, g_xn);    float* pxn   = (float*)p;
    cudaGetSymbolAddress(&p, g_q);     float* pq    = (float*)p;
    cudaGetSymbolAddress(&p, g_k);     float* pk    = (float*)p;
    cudaGetSymbolAddress(&p, g_v);     float* pv    = (float*)p;
    cudaGetSymbolAddress(&p, g_S);     float* pS    = (float*)p;
    cudaGetSymbolAddress(&p, g_vals);  float* pvals = (float*)p;
    cudaGetSymbolAddress(&p, g_o);     float* po    = (float*)p;
    cudaGetSymbolAddress(&p, g_out1);  float* pout1 = (float*)p;
    cudaGetSymbolAddress(&p, g_out2);  float* pout2 = (float*)p;

    embed_kernel<<<TOK, EE>>>(str_fea, comp_fea, atom_table,
                              comp_W, comp_b, pdd_W, pdd_b);

    for (int i = 0; i < LL; i++) {
        const float* g = enc_ln_g + i*EE;
        const float* bta = enc_ln_b + i*EE;

        // xn = LN(x)
        ln_kernel<<<TOK, EE>>>(px, nullptr, g, bta, pxn);

        // qkv = xn @ qkv_W + qkv_b  -> scatter to q/k/v [BH, SEQ, E]
        gemm_kernel<0, EPI_QKV><<<dim3(3*EHH/BN, TOK/BM, 1), 256>>>(
            pxn, EE, 0,
            qkv_W + (size_t)i*EE*3*EHH, 3*EHH, 0,
            nullptr, 0, 0,
            TOK, 3*EHH, EE,
            qkv_b + (size_t)i*3*EHH, nullptr);

        // logits = q @ k^T * scale, masked
        gemm_kernel<1, EPI_LOGITS><<<dim3(SEQ/BN, SEQ/BM, BHH), 256>>>(
            pq, EE, (size_t)SEQ*EE,
            pk, EE, (size_t)SEQ*EE,
            pS, SEQ, (size_t)SEQ*SEQ,
            SEQ, SEQ, EE,
            nullptr, nullptr);

        // weighted softmax in-place on S
        softmax_kernel<<<dim3(SEQ, BHH), 256>>>();

        // vals = attn @ v -> scatter to [B, N, EH]
        gemm_kernel<0, EPI_VALS><<<dim3(EE/BN, SEQ/BM, BHH), 256>>>(
            pS, SEQ, (size_t)SEQ*SEQ,
            pv, EE, (size_t)SEQ*EE,
            nullptr, 0, 0,
            SEQ, EE, SEQ,
            nullptr, nullptr);

        // o = vals @ o_W + o_b
        gemm_kernel<0, EPI_BIAS><<<dim3(EHH/BN, TOK/BM, 1), 256>>>(
            pvals, EHH, 0,
            o_W + (size_t)i*EHH*EHH, EHH, 0,
            po, EHH, 0,
            TOK, EHH, EHH,
            o_b + (size_t)i*EHH, nullptr);

        // out1 = x + o @ out_W + out_b
        gemm_kernel<0, EPI_BIAS_ADD><<<dim3(EE/BN, TOK/BM, 1), 256>>>(
            po, EHH, 0,
            out_W + (size_t)i*EHH*EE, EE, 0,
            pout1, EE, 0,
            TOK, EE, EHH,
            out_b + (size_t)i*EE, px);

        // xn = LN(out1)
        ln_kernel<<<TOK, EE>>>(pout1, nullptr, g, bta, pxn);

        // out2 = mish(xn @ ffn_W + ffn_b)
        gemm_kernel<0, EPI_MISH><<<dim3(EE/BN, TOK/BM, 1), 256>>>(
            pxn, EE, 0,
            ffn_W + (size_t)i*EE*EE, EE, 0,
            pout2, EE, 0,
            TOK, EE, EE,
            ffn_b + (size_t)i*EE, nullptr);

        // x = LN(out1 + out2)
        ln_kernel<<<TOK, EE>>>(pout1, pout2, g, bta, px);
    }

    pool_head_kernel<<<Bb, EE>>>(ln2_g, ln2_b, head_W, head_b, out);
}

// round 2
// speedup vs baseline: 2.2078x; 2.2078x over previous
#include <cuda_runtime.h>
#include <math.h>
#include <stdint.h>

// ---------------- problem constants ----------------
#define Bb   32
#define SEQ  512
#define EE   128
#define HH   8
#define EHH  1024
#define LL   3
#define TOK  (Bb*SEQ)      // 16384 tokens
#define BHH  (Bb*HH)       // 256 (b,h) pairs
#define KF   101
#define ADIM 200

// ---------------- device scratch ----------------
__device__ float g_x    [(size_t)TOK*EE];
__device__ float g_xinit[(size_t)TOK*EE];
__device__ float g_xn   [(size_t)TOK*EE];
__device__ float g_q    [(size_t)BHH*SEQ*EE];
__device__ float g_k    [(size_t)BHH*SEQ*EE];
__device__ float g_v    [(size_t)BHH*SEQ*EE];
__device__ float g_S    [(size_t)BHH*SEQ*SEQ];   // 268 MB logits/attn
__device__ float g_vals [(size_t)TOK*EHH];
__device__ float g_o    [(size_t)TOK*EHH];
__device__ float g_out1 [(size_t)TOK*EE];
__device__ float g_out2 [(size_t)TOK*EE];
__device__ float g_w    [TOK];

// ---------------- helpers ----------------
__device__ __forceinline__ float blkSum128(float v, float* sm) {
    #pragma unroll
    for (int o = 16; o > 0; o >>= 1) v += __shfl_xor_sync(0xffffffffu, v, o);
    int w = threadIdx.x >> 5;
    if ((threadIdx.x & 31) == 0) sm[w] = v;
    __syncthreads();
    float r = sm[0] + sm[1] + sm[2] + sm[3];
    __syncthreads();
    return r;
}

__device__ __forceinline__ uint32_t f2tf(float x) {
    uint32_t r;
    asm("cvt.rna.tf32.f32 %0, %1;" : "=r"(r) : "f"(x));
    return r;
}

__device__ __forceinline__ void mma_tf32(float* d, const uint32_t* a,
                                         uint32_t b0, uint32_t b1) {
    asm volatile(
        "mma.sync.aligned.m16n8k8.row.col.f32.tf32.tf32.f32 "
        "{%0,%1,%2,%3}, {%4,%5,%6,%7}, {%8,%9}, {%0,%1,%2,%3};\n"
        : "+f"(d[0]), "+f"(d[1]), "+f"(d[2]), "+f"(d[3])
        : "r"(a[0]), "r"(a[1]), "r"(a[2]), "r"(a[3]), "r"(b0), "r"(b1));
}

// ---------------- embed ----------------
__global__ void embed_kernel(const float* __restrict__ str_fea,
                             const int*   __restrict__ comp_fea,
                             const float* __restrict__ atom_table,
                             const float* __restrict__ comp_W,
                             const float* __restrict__ comp_b,
                             const float* __restrict__ pdd_W,
                             const float* __restrict__ pdd_b) {
    int t = blockIdx.x;
    int e = threadIdx.x;
    __shared__ float sa[ADIM];
    __shared__ float ss[KF-1];
    const float* sf = str_fea + (size_t)t*KF;
    int idx = comp_fea[t];
    const float* at = atom_table + (size_t)idx*ADIM;
    for (int j = e; j < ADIM; j += EE) sa[j] = at[j];
    for (int j = e; j < KF-1; j += EE) ss[j] = sf[1+j];
    if (e == 0) g_w[t] = sf[0];
    __syncthreads();
    float acc = comp_b[e] + pdd_b[e];
    #pragma unroll 4
    for (int a = 0; a < ADIM; a++) acc = fmaf(sa[a], comp_W[a*EE + e], acc);
    #pragma unroll 4
    for (int j = 0; j < KF-1; j++) acc = fmaf(ss[j], pdd_W[j*EE + e], acc);
    g_x[(size_t)t*EE + e]     = acc;
    g_xinit[(size_t)t*EE + e] = acc;
}

// ---------------- layernorm over E=128 ----------------
__global__ void ln_kernel(const float* __restrict__ src1,
                          const float* __restrict__ src2,
                          const float* __restrict__ gam,
                          const float* __restrict__ bet,
                          float* __restrict__ dst) {
    __shared__ float sm[4];
    int t = blockIdx.x, e = threadIdx.x;
    size_t off = (size_t)t*EE + e;
    float v = src1[off];
    if (src2) v += src2[off];
    float m = blkSum128(v, sm) * (1.f/EE);
    float d = v - m;
    float var = blkSum128(d*d, sm) * (1.f/EE);
    dst[off] = d * rsqrtf(var + 1e-5f) * gam[e] + bet[e];
}

// ---------------- tensor-core tf32 GEMM with epilogues ----------------
// Block tile 128x128x32, 256 threads, 8 warps (4 m x 2 n), warp tile 32x64.
#define BM 128
#define BN 128
#define BK 32
#define PITCH 36

enum { EPI_BIAS=0, EPI_BIAS_ADD=1, EPI_MISH=2, EPI_QKV=3, EPI_LOGITS=4, EPI_VALS=5 };

template<int TB, int EPI>
__global__ __launch_bounds__(256, 2)
void gemm_kernel(const float* __restrict__ A, int lda, size_t sA,
                 const float* __restrict__ B, int ldb, size_t sB,
                 float* __restrict__ C, int ldc, size_t sC,
                 int M, int Nn, int K,
                 const float* __restrict__ bias,
                 const float* __restrict__ addend) {
    int z = blockIdx.z;
    A += (size_t)z * sA;
    B += (size_t)z * sB;
    if (C) C += (size_t)z * sC;
    int bm = blockIdx.y * BM, bn = blockIdx.x * BN;

    __shared__ uint32_t As[BM][PITCH];
    __shared__ uint32_t Bs[BN][PITCH];

    int tid  = threadIdx.x;
    int lane = tid & 31;
    int wid  = tid >> 5;
    int warpM = wid & 3;      // 4 warps over M
    int warpN = wid >> 2;     // 2 warps over N
    int g  = lane >> 2;       // groupID 0..7
    int tg = lane & 3;        // thread-in-group 0..3

    float d[2][8][4];
    #pragma unroll
    for (int mt=0; mt<2; mt++)
        #pragma unroll
        for (int nt=0; nt<8; nt++)
            #pragma unroll
            for (int c=0; c<4; c++) d[mt][nt][c] = 0.f;

    for (int k0 = 0; k0 < K; k0 += BK) {
        // ---- load A tile [BM][BK] (A row-major, k contiguous) ----
        #pragma unroll
        for (int i = 0; i < 4; i++) {
            int e = i*256 + tid;
            int m = e >> 3, kq = e & 7;
            const float4 v = *(const float4*)&A[(size_t)(bm + m)*lda + k0 + kq*4];
            uint32_t* s = &As[m][kq*4];
            s[0] = f2tf(v.x); s[1] = f2tf(v.y); s[2] = f2tf(v.z); s[3] = f2tf(v.w);
        }
        // ---- load B tile -> Bs[n][k] ----
        if (TB == 1) {  // B is [N][K], k contiguous
            #pragma unroll
            for (int i = 0; i < 4; i++) {
                int e = i*256 + tid;
                int n = e >> 3, kq = e & 7;
                const float4 v = *(const float4*)&B[(size_t)(bn + n)*ldb + k0 + kq*4];
                uint32_t* s = &Bs[n][kq*4];
                s[0] = f2tf(v.x); s[1] = f2tf(v.y); s[2] = f2tf(v.z); s[3] = f2tf(v.w);
            }
        } else {        // B is [K][N], n contiguous -> transpose-store
            #pragma unroll
            for (int i = 0; i < 16; i++) {
                int e = i*256 + tid;
                int k = e >> 7, n = e & 127;
                Bs[n][k] = f2tf(B[(size_t)(k0 + k)*ldb + bn + n]);
            }
        }
        __syncthreads();

        // ---- mma over 4 k8 steps ----
        #pragma unroll
        for (int ks = 0; ks < BK; ks += 8) {
            uint32_t a[2][4];
            #pragma unroll
            for (int mt = 0; mt < 2; mt++) {
                int m0 = warpM*32 + mt*16 + g;
                a[mt][0] = As[m0    ][ks + tg];
                a[mt][1] = As[m0 + 8][ks + tg];
                a[mt][2] = As[m0    ][ks + tg + 4];
                a[mt][3] = As[m0 + 8][ks + tg + 4];
            }
            #pragma unroll
            for (int nt = 0; nt < 8; nt++) {
                int n0 = warpN*64 + nt*8 + g;
                uint32_t b0 = Bs[n0][ks + tg];
                uint32_t b1 = Bs[n0][ks + tg + 4];
                mma_tf32(d[0][nt], a[0], b0, b1);
                mma_tf32(d[1][nt], a[1], b0, b1);
            }
        }
        __syncthreads();
    }

    // ---- epilogue ----
    #pragma unroll
    for (int mt = 0; mt < 2; mt++) {
        #pragma unroll
        for (int nt = 0; nt < 8; nt++) {
            #pragma unroll
            for (int half = 0; half < 2; half++) {
                int m = bm + warpM*32 + mt*16 + g + half*8;
                int n = bn + warpN*64 + nt*8 + 2*tg;
                float v0 = d[mt][nt][half*2 + 0];
                float v1 = d[mt][nt][half*2 + 1];
                if (EPI == EPI_BIAS) {
                    float2 r = make_float2(v0 + bias[n], v1 + bias[n+1]);
                    *(float2*)&C[(size_t)m*ldc + n] = r;
                } else if (EPI == EPI_BIAS_ADD) {
                    const float2 ad = *(const float2*)&addend[(size_t)m*ldc + n];
                    float2 r = make_float2(v0 + bias[n] + ad.x, v1 + bias[n+1] + ad.y);
                    *(float2*)&C[(size_t)m*ldc + n] = r;
                } else if (EPI == EPI_MISH) {
                    float x0 = v0 + bias[n],  x1 = v1 + bias[n+1];
                    float s0 = (x0 > 20.f) ? x0 : log1pf(expf(x0));
                    float s1 = (x1 > 20.f) ? x1 : log1pf(expf(x1));
                    float2 r = make_float2(x0 * tanhf(s0), x1 * tanhf(s1));
                    *(float2*)&C[(size_t)m*ldc + n] = r;
                } else if (EPI == EPI_QKV) {
                    #pragma unroll
                    for (int j = 0; j < 2; j++) {
                        int nn2 = n + j;
                        float val = ((j == 0) ? v0 : v1) + bias[nn2];
                        int b = m >> 9, tok = m & 511;
                        int h = nn2 / 384, rem = nn2 % 384;
                        int r = rem >> 7, dd = rem & 127;
                        float* dst = (r == 0) ? g_q : (r == 1) ? g_k : g_v;
                        dst[((size_t)(b*HH + h)*SEQ + tok)*EE + dd] = val;
                    }
                } else if (EPI == EPI_LOGITS) {
                    int b = z >> 3;
                    bool mq = g_w[b*SEQ + m] > 0.f;
                    float2 r;
                    r.x = (mq && (g_w[b*SEQ + n]   > 0.f)) ? v0 * 0.08838834764831845f : -9.0e15f;
                    r.y = (mq && (g_w[b*SEQ + n+1] > 0.f)) ? v1 * 0.08838834764831845f : -9.0e15f;
                    *(float2*)&C[(size_t)m*ldc + n] = r;
                } else { // EPI_VALS
                    int b = z >> 3, h = z & 7;
                    float2 r = make_float2(v0, v1);
                    *(float2*)&g_vals[((size_t)(b*SEQ + m))*EHH + h*EE + n] = r;
                }
            }
        }
    }
}

// ---------------- softmax with key-weight (w_attn) ----------------
__global__ void softmax_kernel() {
    int q  = blockIdx.x, bh = blockIdx.y;
    int b  = bh >> 3;
    float* row = g_S + ((size_t)bh*SEQ + q)*SEQ;
    int tid = threadIdx.x;
    __shared__ float sm[8];
    int w = tid >> 5, lane = tid & 31;

    float l0 = row[tid], l1 = row[tid + 256];
    float mx = fmaxf(l0, l1);
    #pragma unroll
    for (int o=16;o>0;o>>=1) mx = fmaxf(mx, __shfl_xor_sync(0xffffffffu, mx, o));
    if (lane==0) sm[w] = mx;
    __syncthreads();
    float m = sm[0];
    #pragma unroll
    for (int i=1;i<8;i++) m = fmaxf(m, sm[i]);
    __syncthreads();

    float w0 = g_w[b*SEQ + tid], w1 = g_w[b*SEQ + tid + 256];
    float e0 = w0 * expf(l0 - m);
    float e1 = w1 * expf(l1 - m);
    float s = e0 + e1;
    #pragma unroll
    for (int o=16;o>0;o>>=1) s += __shfl_xor_sync(0xffffffffu, s, o);
    if (lane==0) sm[w] = s;
    __syncthreads();
    float tot = sm[0];
    #pragma unroll
    for (int i=1;i<8;i++) tot += sm[i];

    float inv = 1.f / tot;
    row[tid]       = e0 * inv;
    row[tid + 256] = e1 * inv;
}

// ---------------- final: weighted pool + LN + head ----------------
__global__ void pool_head_kernel(const float* __restrict__ ln2_g,
                                 const float* __restrict__ ln2_b,
                                 const float* __restrict__ head_W,
                                 const float* __restrict__ head_b,
                                 float* __restrict__ out) {
    __shared__ float sm[4];
    int b = blockIdx.x, e = threadIdx.x;
    const float* xb  = g_x     + (size_t)b*SEQ*EE;
    const float* xib = g_xinit + (size_t)b*SEQ*EE;
    float s = 0.f;
    for (int n = 0; n < SEQ; n++)
        s = fmaf(g_w[b*SEQ + n], xb[n*EE + e] + xib[n*EE + e], s);
    float m = blkSum128(s, sm) * (1.f/EE);
    float d = s - m;
    float var = blkSum128(d*d, sm) * (1.f/EE);
    float p = d * rsqrtf(var + 1e-5f) * ln2_g[e] + ln2_b[e];
    float dot = blkSum128(p * head_W[e], sm);
    if (e == 0) out[b] = dot + head_b[0];
}

// ---------------- host launch ----------------
extern "C" void kernel_launch(void* const* d_in, const int* in_sizes, int n_in,
                              void* d_out, int out_size) {
    (void)in_sizes; (void)n_in; (void)out_size;
    const float* str_fea   = (const float*)d_in[0];
    const int*   comp_fea  = (const int*)  d_in[1];
    const float* atom_table= (const float*)d_in[3];
    const float* comp_W    = (const float*)d_in[4];
    const float* comp_b    = (const float*)d_in[5];
    const float* pdd_W     = (const float*)d_in[6];
    const float* pdd_b     = (const float*)d_in[7];
    const float* enc_ln_g  = (const float*)d_in[8];
    const float* enc_ln_b  = (const float*)d_in[9];
    const float* qkv_W     = (const float*)d_in[10];
    const float* qkv_b     = (const float*)d_in[11];
    const float* o_W       = (const float*)d_in[12];
    const float* o_b       = (const float*)d_in[13];
    const float* out_W     = (const float*)d_in[14];
    const float* out_b     = (const float*)d_in[15];
    const float* ffn_W     = (const float*)d_in[16];
    const float* ffn_b     = (const float*)d_in[17];
    const float* ln2_g     = (const float*)d_in[18];
    const float* ln2_b     = (const float*)d_in[19];
    const float* head_W    = (const float*)d_in[20];
    const float* head_b    = (const float*)d_in[21];
    float* out = (float*)d_out;

    void* p;
    cudaGetSymbolAddress(&p, g_x);     float* px    = (float*)p;
    cudaGetSymbolAddress(&p, g_xn);    float* pxn   = (float*)p;
    cudaGetSymbolAddress(&p, g_q);     float* pq    = (float*)p;
    cudaGetSymbolAddress(&p, g_k);     float* pk    = (float*)p;
    cudaGetSymbolAddress(&p, g_v);     float* pv    = (float*)p;
    cudaGetSymbolAddress(&p, g_S);     float* pS    = (float*)p;
    cudaGetSymbolAddress(&p, g_vals);  float* pvals = (float*)p;
    cudaGetSymbolAddress(&p, g_o);     float* po    = (float*)p;
    cudaGetSymbolAddress(&p, g_out1);  float* pout1 = (float*)p;
    cudaGetSymbolAddress(&p, g_out2);  float* pout2 = (float*)p;

    embed_kernel<<<TOK, EE>>>(str_fea, comp_fea, atom_table,
                              comp_W, comp_b, pdd_W, pdd_b);

    for (int i = 0; i < LL; i++) {
        const float* g = enc_ln_g + i*EE;
        const float* bta = enc_ln_b + i*EE;

        ln_kernel<<<TOK, EE>>>(px, nullptr, g, bta, pxn);

        // qkv = xn @ qkv_W + qkv_b -> scatter q/k/v [BH, SEQ, E]
        gemm_kernel<0, EPI_QKV><<<dim3(3*EHH/BN, TOK/BM, 1), 256>>>(
            pxn, EE, 0,
            qkv_W + (size_t)i*EE*3*EHH, 3*EHH, 0,
            nullptr, 0, 0,
            TOK, 3*EHH, EE,
            qkv_b + (size_t)i*3*EHH, nullptr);

        // logits = q @ k^T * scale, masked
        gemm_kernel<1, EPI_LOGITS><<<dim3(SEQ/BN, SEQ/BM, BHH), 256>>>(
            pq, EE, (size_t)SEQ*EE,
            pk, EE, (size_t)SEQ*EE,
            pS, SEQ, (size_t)SEQ*SEQ,
            SEQ, SEQ, EE,
            nullptr, nullptr);

        softmax_kernel<<<dim3(SEQ, BHH), 256>>>();

        // vals = attn @ v -> scatter [B, N, EH]
        gemm_kernel<0, EPI_VALS><<<dim3(EE/BN, SEQ/BM, BHH), 256>>>(
            pS, SEQ, (size_t)SEQ*SEQ,
            pv, EE, (size_t)SEQ*EE,
            nullptr, 0, 0,
            SEQ, EE, SEQ,
            nullptr, nullptr);

        // o = vals @ o_W + o_b
        gemm_kernel<0, EPI_BIAS><<<dim3(EHH/BN, TOK/BM, 1), 256>>>(
            pvals, EHH, 0,
            o_W + (size_t)i*EHH*EHH, EHH, 0,
            po, EHH, 0,
            TOK, EHH, EHH,
            o_b + (size_t)i*EHH, nullptr);

        // out1 = x + o @ out_W + out_b
        gemm_kernel<0, EPI_BIAS_ADD><<<dim3(EE/BN, TOK/BM, 1), 256>>>(
            po, EHH, 0,
            out_W + (size_t)i*EHH*EE, EE, 0,
            pout1, EE, 0,
            TOK, EE, EHH,
            out_b + (size_t)i*EE, px);

        ln_kernel<<<TOK, EE>>>(pout1, nullptr, g, bta, pxn);

        // out2 = mish(xn @ ffn_W + ffn_b)
        gemm_kernel<0, EPI_MISH><<<dim3(EE/BN, TOK/BM, 1), 256>>>(
            pxn, EE, 0,
            ffn_W + (size_t)i*EE*EE, EE, 0,
            pout2, EE, 0,
            TOK, EE, EE,
            ffn_b + (size_t)i*EE, nullptr);

        ln_kernel<<<TOK, EE>>>(pout1, pout2, g, bta, px);
    }

    pool_head_kernel<<<Bb, EE>>>(ln2_g, ln2_b, head_W, head_b, out);
}

// round 10
// speedup vs baseline: 2.3837x; 1.0797x over previous
#include <cuda_runtime.h>
#include <cuda_bf16.h>
#include <math.h>
#include <stdint.h>

// ---------------- problem constants ----------------
#define Bb   32
#define SEQ  512
#define EE   128
#define HH   8
#define EHH  1024
#define LL   3
#define TOK  (Bb*SEQ)      // 16384 tokens
#define BHH  (Bb*HH)       // 256 (b,h) pairs
#define KF   101
#define ADIM 200
#define SCALE 0.08838834764831845f

// ---------------- device scratch ----------------
__device__ float g_x    [(size_t)TOK*EE];
__device__ float g_xinit[(size_t)TOK*EE];
__device__ float g_xn   [(size_t)TOK*EE];
__device__ float g_q    [(size_t)BHH*SEQ*EE];
__device__ float g_k    [(size_t)BHH*SEQ*EE];
__device__ float g_v    [(size_t)BHH*SEQ*EE];
__device__ float g_vals [(size_t)TOK*EHH];
__device__ float g_o    [(size_t)TOK*EHH];
__device__ float g_out1 [(size_t)TOK*EE];
__device__ float g_out2 [(size_t)TOK*EE];
__device__ float g_w    [TOK];

// ---------------- helpers ----------------
__device__ __forceinline__ float blkSum128(float v, float* sm) {
    #pragma unroll
    for (int o = 16; o > 0; o >>= 1) v += __shfl_xor_sync(0xffffffffu, v, o);
    int w = threadIdx.x >> 5;
    if ((threadIdx.x & 31) == 0) sm[w] = v;
    __syncthreads();
    float r = sm[0] + sm[1] + sm[2] + sm[3];
    __syncthreads();
    return r;
}

// split two floats into packed bf16 hi / lo words (low 16 bits = first arg)
__device__ __forceinline__ void bsplit2(float x, float y, uint32_t& hi, uint32_t& lo) {
    __nv_bfloat16 xh = __float2bfloat16(x);
    __nv_bfloat16 yh = __float2bfloat16(y);
    float xr = x - __bfloat162float(xh);
    float yr = y - __bfloat162float(yh);
    __nv_bfloat162 h2 = __halves2bfloat162(xh, yh);
    __nv_bfloat162 l2 = __halves2bfloat162(__float2bfloat16(xr), __float2bfloat16(yr));
    hi = *reinterpret_cast<uint32_t*>(&h2);
    lo = *reinterpret_cast<uint32_t*>(&l2);
}

__device__ __forceinline__ void mma_bf16(float* d, const uint32_t* a,
                                         uint32_t b0, uint32_t b1) {
    asm volatile(
        "mma.sync.aligned.m16n8k16.row.col.f32.bf16.bf16.f32 "
        "{%0,%1,%2,%3}, {%4,%5,%6,%7}, {%8,%9}, {%0,%1,%2,%3};\n"
        : "+f"(d[0]), "+f"(d[1]), "+f"(d[2]), "+f"(d[3])
        : "r"(a[0]), "r"(a[1]), "r"(a[2]), "r"(a[3]), "r"(b0), "r"(b1));
}

// ---------------- embed ----------------
__global__ void embed_kernel(const float* __restrict__ str_fea,
                             const int*   __restrict__ comp_fea,
                             const float* __restrict__ atom_table,
                             const float* __restrict__ comp_W,
                             const float* __restrict__ comp_b,
                             const float* __restrict__ pdd_W,
                             const float* __restrict__ pdd_b) {
    int t = blockIdx.x;
    int e = threadIdx.x;
    __shared__ float sa[ADIM];
    __shared__ float ss[KF-1];
    const float* sf = str_fea + (size_t)t*KF;
    int idx = comp_fea[t];
    const float* at = atom_table + (size_t)idx*ADIM;
    for (int j = e; j < ADIM; j += EE) sa[j] = at[j];
    for (int j = e; j < KF-1; j += EE) ss[j] = sf[1+j];
    if (e == 0) g_w[t] = sf[0];
    __syncthreads();
    float acc = comp_b[e] + pdd_b[e];
    #pragma unroll 4
    for (int a = 0; a < ADIM; a++) acc = fmaf(sa[a], comp_W[a*EE + e], acc);
    #pragma unroll 4
    for (int j = 0; j < KF-1; j++) acc = fmaf(ss[j], pdd_W[j*EE + e], acc);
    g_x[(size_t)t*EE + e]     = acc;
    g_xinit[(size_t)t*EE + e] = acc;
}

// ---------------- layernorm over E=128 ----------------
__global__ void ln_kernel(const float* __restrict__ src1,
                          const float* __restrict__ src2,
                          const float* __restrict__ gam,
                          const float* __restrict__ bet,
                          float* __restrict__ dst) {
    __shared__ float sm[4];
    int t = blockIdx.x, e = threadIdx.x;
    size_t off = (size_t)t*EE + e;
    float v = src1[off];
    if (src2) v += src2[off];
    float m = blkSum128(v, sm) * (1.f/EE);
    float d = v - m;
    float var = blkSum128(d*d, sm) * (1.f/EE);
    dst[off] = d * rsqrtf(var + 1e-5f) * gam[e] + bet[e];
}

// ---------------- bf16x2 split GEMM (3-mma), B row-major [K][N] ----------------
// Block 128x128x32, 256 threads, warps 4(m) x 2(n), warp tile 32x64.
#define BM 128
#define BN 128
#define BK 32
#define GP 20   // pitch in words for [row][kp] tiles, kp range 16

enum { EPI_BIAS=0, EPI_BIAS_ADD=1, EPI_MISH=2, EPI_QKV=3 };

template<int EPI>
__global__ __launch_bounds__(256, 2)
void gemm_kernel(const float* __restrict__ A, int lda,
                 const float* __restrict__ B, int ldb,
                 float* __restrict__ C, int ldc,
                 int K,
                 const float* __restrict__ bias,
                 const float* __restrict__ addend) {
    int bm = blockIdx.y * BM, bn = blockIdx.x * BN;

    __shared__ uint32_t Ah[BM][GP], Al[BM][GP];
    __shared__ uint32_t Bh[BN][GP], Bl[BN][GP];

    int tid  = threadIdx.x;
    int lane = tid & 31;
    int wid  = tid >> 5;
    int warpM = wid & 3;
    int warpN = wid >> 2;
    int g  = lane >> 2;
    int tg = lane & 3;

    float d[2][8][4];
    #pragma unroll
    for (int mt=0; mt<2; mt++)
        #pragma unroll
        for (int nt=0; nt<8; nt++)
            #pragma unroll
            for (int c=0; c<4; c++) d[mt][nt][c] = 0.f;

    for (int k0 = 0; k0 < K; k0 += BK) {
        // A tile: [BM][BK], k contiguous in gmem
        #pragma unroll
        for (int i = 0; i < 4; i++) {
            int e = i*256 + tid;
            int m = e >> 3, c = e & 7;
            const float4 v = *(const float4*)&A[(size_t)(bm + m)*lda + k0 + 4*c];
            bsplit2(v.x, v.y, Ah[m][2*c],   Al[m][2*c]);
            bsplit2(v.z, v.w, Ah[m][2*c+1], Al[m][2*c+1]);
        }
        // B tile: B[K][N] n contiguous -> Bs[n][kp]
        #pragma unroll
        for (int i = 0; i < 8; i++) {
            int e = i*256 + tid;
            int n = e & 127, kp = e >> 7;
            float b0 = B[(size_t)(k0 + 2*kp    )*ldb + bn + n];
            float b1 = B[(size_t)(k0 + 2*kp + 1)*ldb + bn + n];
            bsplit2(b0, b1, Bh[n][kp], Bl[n][kp]);
        }
        __syncthreads();

        #pragma unroll
        for (int js = 0; js < 2; js++) {
            int kb = js*8 + tg;
            uint32_t ah[2][4], al[2][4];
            #pragma unroll
            for (int mt = 0; mt < 2; mt++) {
                int m0 = warpM*32 + mt*16 + g;
                ah[mt][0] = Ah[m0  ][kb];   al[mt][0] = Al[m0  ][kb];
                ah[mt][1] = Ah[m0+8][kb];   al[mt][1] = Al[m0+8][kb];
                ah[mt][2] = Ah[m0  ][kb+4]; al[mt][2] = Al[m0  ][kb+4];
                ah[mt][3] = Ah[m0+8][kb+4]; al[mt][3] = Al[m0+8][kb+4];
            }
            #pragma unroll
            for (int nt = 0; nt < 8; nt++) {
                int n0 = warpN*64 + nt*8 + g;
                uint32_t bh0 = Bh[n0][kb], bh1 = Bh[n0][kb+4];
                uint32_t bl0 = Bl[n0][kb], bl1 = Bl[n0][kb+4];
                #pragma unroll
                for (int mt = 0; mt < 2; mt++) {
                    mma_bf16(d[mt][nt], ah[mt], bh0, bh1);
                    mma_bf16(d[mt][nt], ah[mt], bl0, bl1);
                    mma_bf16(d[mt][nt], al[mt], bh0, bh1);
                }
            }
        }
        __syncthreads();
    }

    // epilogue
    #pragma unroll
    for (int mt = 0; mt < 2; mt++) {
        #pragma unroll
        for (int nt = 0; nt < 8; nt++) {
            #pragma unroll
            for (int half = 0; half < 2; half++) {
                int m = bm + warpM*32 + mt*16 + g + half*8;
                int n = bn + warpN*64 + nt*8 + 2*tg;
                float v0 = d[mt][nt][half*2 + 0];
                float v1 = d[mt][nt][half*2 + 1];
                if (EPI == EPI_BIAS) {
                    float2 r = make_float2(v0 + bias[n], v1 + bias[n+1]);
                    *(float2*)&C[(size_t)m*ldc + n] = r;
                } else if (EPI == EPI_BIAS_ADD) {
                    const float2 ad = *(const float2*)&addend[(size_t)m*ldc + n];
                    float2 r = make_float2(v0 + bias[n] + ad.x, v1 + bias[n+1] + ad.y);
                    *(float2*)&C[(size_t)m*ldc + n] = r;
                } else if (EPI == EPI_MISH) {
                    float x0 = v0 + bias[n],  x1 = v1 + bias[n+1];
                    float s0 = (x0 > 20.f) ? x0 : log1pf(expf(x0));
                    float s1 = (x1 > 20.f) ? x1 : log1pf(expf(x1));
                    float2 r = make_float2(x0 * tanhf(s0), x1 * tanhf(s1));
                    *(float2*)&C[(size_t)m*ldc + n] = r;
                } else { // EPI_QKV: scatter to q/k/v [BH][SEQ][E], scale folded into q
                    #pragma unroll
                    for (int j = 0; j < 2; j++) {
                        int nn2 = n + j;
                        float val = ((j == 0) ? v0 : v1) + bias[nn2];
                        int b = m >> 9, tok = m & 511;
                        int h = nn2 / 384, rem = nn2 % 384;
                        int r = rem >> 7, dd = rem & 127;
                        if (r == 0) val *= SCALE;
                        float* dst = (r == 0) ? g_q : (r == 1) ? g_k : g_v;
                        dst[((size_t)(b*HH + h)*SEQ + tok)*EE + dd] = val;
                    }
                }
            }
        }
    }
}

// ---------------- fused flash attention ----------------
// grid (4 qtiles, 256 bh), 256 threads = 8 warps, each warp owns 16 q-rows.
// Q tile 128 x 128d, K tile 64 keys, V tile 64 x 128d. 8 K-tiles cover SEQ=512.
#define QP 68   // pitch for [row][kp(d)=64] tiles
#define VP 36   // pitch for [d][kp(key)=32] tiles
#define NKT (SEQ/64)   // 8 key tiles

// dynamic smem word offsets
#define OFF_QH 0
#define OFF_QL (OFF_QH + 128*QP)
#define OFF_KH (OFF_QL + 128*QP)
#define OFF_KL (OFF_KH + 64*QP)
#define OFF_VH (OFF_KL + 64*QP)
#define OFF_VL (OFF_VH + 128*VP)
#define OFF_WS (OFF_VL + 128*VP)
#define FLASH_WORDS (OFF_WS + 64)

__global__ __launch_bounds__(256, 1)
void flash_kernel() {
    extern __shared__ uint32_t smx[];
    uint32_t* Qh = smx + OFF_QH;
    uint32_t* Ql = smx + OFF_QL;
    uint32_t* Kh = smx + OFF_KH;
    uint32_t* Kl = smx + OFF_KL;
    uint32_t* Vh = smx + OFF_VH;
    uint32_t* Vl = smx + OFF_VL;
    float*    ws = (float*)(smx + OFF_WS);

    int qt = blockIdx.x, bh = blockIdx.y;
    int b = bh >> 3, h = bh & 7;
    int tid = threadIdx.x;
    int lane = tid & 31;
    int wid = tid >> 5;
    int g = lane >> 2, tg = lane & 3;

    // load Q tile (scale already folded in)
    const float* Qg = g_q + ((size_t)bh*SEQ + qt*128)*EE;
    #pragma unroll
    for (int i = 0; i < 16; i++) {
        int e = i*256 + tid;
        int row = e >> 5, d4 = e & 31;
        const float4 v = *(const float4*)&Qg[row*EE + 4*d4];
        bsplit2(v.x, v.y, Qh[row*QP + 2*d4],   Ql[row*QP + 2*d4]);
        bsplit2(v.z, v.w, Qh[row*QP + 2*d4+1], Ql[row*QP + 2*d4+1]);
    }

    int rowg = qt*128 + wid*16 + g;   // global row of "half 0"
    bool mq0 = g_w[b*SEQ + rowg]     > 0.f;
    bool mq1 = g_w[b*SEQ + rowg + 8] > 0.f;

    float m_run[2] = {-9.0e15f, -9.0e15f};
    float l_run[2] = {0.f, 0.f};
    float o[16][4];
    #pragma unroll
    for (int dt = 0; dt < 16; dt++)
        #pragma unroll
        for (int c = 0; c < 4; c++) o[dt][c] = 0.f;

    for (int kt = 0; kt < NKT; kt++) {
        __syncthreads();   // previous P@V done before overwriting K/V tiles
        if (tid < 64) ws[tid] = g_w[b*SEQ + kt*64 + tid];
        const float* Kg = g_k + ((size_t)bh*SEQ + kt*64)*EE;
        #pragma unroll
        for (int i = 0; i < 8; i++) {
            int e = i*256 + tid;
            int row = e >> 5, d4 = e & 31;
            const float4 v = *(const float4*)&Kg[row*EE + 4*d4];
            bsplit2(v.x, v.y, Kh[row*QP + 2*d4],   Kl[row*QP + 2*d4]);
            bsplit2(v.z, v.w, Kh[row*QP + 2*d4+1], Kl[row*QP + 2*d4+1]);
        }
        const float* Vg = g_v + ((size_t)bh*SEQ + kt*64)*EE;
        #pragma unroll
        for (int i = 0; i < 4; i++) {
            int e = i*256 + tid;
            int d4 = e & 31, kp = e >> 5;   // kp 0..31 (key pair)
            const float4 ve = *(const float4*)&Vg[(2*kp  )*EE + 4*d4];
            const float4 vo = *(const float4*)&Vg[(2*kp+1)*EE + 4*d4];
            bsplit2(ve.x, vo.x, Vh[(4*d4+0)*VP + kp], Vl[(4*d4+0)*VP + kp]);
            bsplit2(ve.y, vo.y, Vh[(4*d4+1)*VP + kp], Vl[(4*d4+1)*VP + kp]);
            bsplit2(ve.z, vo.z, Vh[(4*d4+2)*VP + kp], Vl[(4*d4+2)*VP + kp]);
            bsplit2(ve.w, vo.w, Vh[(4*d4+3)*VP + kp], Vl[(4*d4+3)*VP + kp]);
        }
        __syncthreads();

        // ---- S = Q @ K^T (warp: 16 rows x 64 keys) ----
        float s[8][4];
        #pragma unroll
        for (int nt=0; nt<8; nt++)
            #pragma unroll
            for (int c=0; c<4; c++) s[nt][c] = 0.f;

        int m0 = wid*16 + g;
        #pragma unroll
        for (int ks = 0; ks < 8; ks++) {
            int kb = ks*8 + tg;
            uint32_t ah[4], al[4];
            ah[0] = Qh[m0*QP + kb];       al[0] = Ql[m0*QP + kb];
            ah[1] = Qh[(m0+8)*QP + kb];   al[1] = Ql[(m0+8)*QP + kb];
            ah[2] = Qh[m0*QP + kb+4];     al[2] = Ql[m0*QP + kb+4];
            ah[3] = Qh[(m0+8)*QP + kb+4]; al[3] = Ql[(m0+8)*QP + kb+4];
            #pragma unroll
            for (int nt = 0; nt < 8; nt++) {
                int n0 = nt*8 + g;
                uint32_t bh0 = Kh[n0*QP + kb], bh1 = Kh[n0*QP + kb+4];
                uint32_t bl0 = Kl[n0*QP + kb], bl1 = Kl[n0*QP + kb+4];
                mma_bf16(s[nt], ah, bh0, bh1);
                mma_bf16(s[nt], ah, bl0, bl1);
                mma_bf16(s[nt], al, bh0, bh1);
            }
        }

        // ---- mask + online softmax stats (warp-local rows) ----
        float tmax[2] = {-9.0e15f, -9.0e15f};
        #pragma unroll
        for (int nt = 0; nt < 8; nt++) {
            int col0 = nt*8 + 2*tg;
            #pragma unroll
            for (int c = 0; c < 4; c++) {
                bool mk = ws[col0 + (c & 1)] > 0.f;
                bool mr = (c < 2) ? mq0 : mq1;
                float v = (mk && mr) ? s[nt][c] : -9.0e15f;
                s[nt][c] = v;
                int hf = c >> 1;
                tmax[hf] = fmaxf(tmax[hf], v);
            }
        }
        #pragma unroll
        for (int off = 1; off <= 2; off <<= 1) {
            tmax[0] = fmaxf(tmax[0], __shfl_xor_sync(0xffffffffu, tmax[0], off));
            tmax[1] = fmaxf(tmax[1], __shfl_xor_sync(0xffffffffu, tmax[1], off));
        }
        float nm0 = fmaxf(m_run[0], tmax[0]);
        float nm1 = fmaxf(m_run[1], tmax[1]);
        float a0 = __expf(m_run[0] - nm0);
        float a1 = __expf(m_run[1] - nm1);
        float rs[2] = {0.f, 0.f};
        #pragma unroll
        for (int nt = 0; nt < 8; nt++) {
            int col0 = nt*8 + 2*tg;
            #pragma unroll
            for (int c = 0; c < 4; c++) {
                float nm = (c < 2) ? nm0 : nm1;
                float p = ws[col0 + (c & 1)] * __expf(s[nt][c] - nm);
                s[nt][c] = p;
                rs[c >> 1] += p;
            }
        }
        #pragma unroll
        for (int off = 1; off <= 2; off <<= 1) {
            rs[0] += __shfl_xor_sync(0xffffffffu, rs[0], off);
            rs[1] += __shfl_xor_sync(0xffffffffu, rs[1], off);
        }
        l_run[0] = a0*l_run[0] + rs[0];
        l_run[1] = a1*l_run[1] + rs[1];
        m_run[0] = nm0; m_run[1] = nm1;
        #pragma unroll
        for (int dt = 0; dt < 16; dt++) {
            o[dt][0] *= a0; o[dt][1] *= a0;
            o[dt][2] *= a1; o[dt][3] *= a1;
        }

        // ---- O += P @ V (P from registers, FA2 C->A fragment reuse) ----
        #pragma unroll
        for (int j = 0; j < 4; j++) {
            uint32_t pah[4], pal[4];
            bsplit2(s[2*j  ][0], s[2*j  ][1], pah[0], pal[0]);
            bsplit2(s[2*j  ][2], s[2*j  ][3], pah[1], pal[1]);
            bsplit2(s[2*j+1][0], s[2*j+1][1], pah[2], pal[2]);
            bsplit2(s[2*j+1][2], s[2*j+1][3], pah[3], pal[3]);
            int kb = j*8 + tg;
            #pragma unroll
            for (int dt = 0; dt < 16; dt++) {
                int n0 = dt*8 + g;
                uint32_t vh0 = Vh[n0*VP + kb], vh1 = Vh[n0*VP + kb+4];
                uint32_t vl0 = Vl[n0*VP + kb], vl1 = Vl[n0*VP + kb+4];
                mma_bf16(o[dt], pah, vh0, vh1);
                mma_bf16(o[dt], pah, vl0, vl1);
                mma_bf16(o[dt], pal, vh0, vh1);
            }
        }
    }

    // ---- normalize + store to g_vals [B, N, EH] ----
    float inv0 = 1.f / l_run[0];
    float inv1 = 1.f / l_run[1];
    float* dst0 = g_vals + ((size_t)(b*SEQ) + qt*128 + wid*16 + g)*EHH + h*EE;
    float* dst1 = dst0 + (size_t)8*EHH;
    #pragma unroll
    for (int dt = 0; dt < 16; dt++) {
        int d0 = dt*8 + 2*tg;
        *(float2*)&dst0[d0] = make_float2(o[dt][0]*inv0, o[dt][1]*inv0);
        *(float2*)&dst1[d0] = make_float2(o[dt][2]*inv1, o[dt][3]*inv1);
    }
}

// ---------------- final: weighted pool + LN + head ----------------
__global__ void pool_head_kernel(const float* __restrict__ ln2_g,
                                 const float* __restrict__ ln2_b,
                                 const float* __restrict__ head_W,
                                 const float* __restrict__ head_b,
                                 float* __restrict__ out) {
    __shared__ float sm[4];
    int b = blockIdx.x, e = threadIdx.x;
    const float* xb  = g_x     + (size_t)b*SEQ*EE;
    const float* xib = g_xinit + (size_t)b*SEQ*EE;
    float s = 0.f;
    for (int n = 0; n < SEQ; n++)
        s = fmaf(g_w[b*SEQ + n], xb[n*EE + e] + xib[n*EE + e], s);
    float m = blkSum128(s, sm) * (1.f/EE);
    float d = s - m;
    float var = blkSum128(d*d, sm) * (1.f/EE);
    float p = d * rsqrtf(var + 1e-5f) * ln2_g[e] + ln2_b[e];
    float dot = blkSum128(p * head_W[e], sm);
    if (e == 0) out[b] = dot + head_b[0];
}

// ---------------- host launch ----------------
extern "C" void kernel_launch(void* const* d_in, const int* in_sizes, int n_in,
                              void* d_out, int out_size) {
    (void)in_sizes; (void)n_in; (void)out_size;
    const float* str_fea   = (const float*)d_in[0];
    const int*   comp_fea  = (const int*)  d_in[1];
    const float* atom_table= (const float*)d_in[3];
    const float* comp_W    = (const float*)d_in[4];
    const float* comp_b    = (const float*)d_in[5];
    const float* pdd_W     = (const float*)d_in[6];
    const float* pdd_b     = (const float*)d_in[7];
    const float* enc_ln_g  = (const float*)d_in[8];
    const float* enc_ln_b  = (const float*)d_in[9];
    const float* qkv_W     = (const float*)d_in[10];
    const float* qkv_b     = (const float*)d_in[11];
    const float* o_W       = (const float*)d_in[12];
    const float* o_b       = (const float*)d_in[13];
    const float* out_W     = (const float*)d_in[14];
    const float* out_b     = (const float*)d_in[15];
    const float* ffn_W     = (const float*)d_in[16];
    const float* ffn_b     = (const float*)d_in[17];
    const float* ln2_g     = (const float*)d_in[18];
    const float* ln2_b     = (const float*)d_in[19];
    const float* head_W    = (const float*)d_in[20];
    const float* head_b    = (const float*)d_in[21];
    float* out = (float*)d_out;

    void* p;
    cudaGetSymbolAddress(&p, g_x);     float* px    = (float*)p;
    cudaGetSymbolAddress(&p, g_xn);    float* pxn   = (float*)p;
    cudaGetSymbolAddress(&p, g_vals);  float* pvals = (float*)p;
    cudaGetSymbolAddress(&p, g_o);     float* po    = (float*)p;
    cudaGetSymbolAddress(&p, g_out1);  float* pout1 = (float*)p;
    cudaGetSymbolAddress(&p, g_out2);  float* pout2 = (float*)p;

    cudaFuncSetAttribute(flash_kernel,
                         cudaFuncAttributeMaxDynamicSharedMemorySize,
                         FLASH_WORDS * 4);

    embed_kernel<<<TOK, EE>>>(str_fea, comp_fea, atom_table,
                              comp_W, comp_b, pdd_W, pdd_b);

    for (int i = 0; i < LL; i++) {
        const float* g = enc_ln_g + i*EE;
        const float* bta = enc_ln_b + i*EE;

        ln_kernel<<<TOK, EE>>>(px, nullptr, g, bta, pxn);

        // qkv projection -> scatter q (pre-scaled) / k / v
        gemm_kernel<EPI_QKV><<<dim3(3*EHH/BN, TOK/BM), 256>>>(
            pxn, EE, qkv_W + (size_t)i*EE*3*EHH, 3*EHH,
            nullptr, 0, EE, qkv_b + (size_t)i*3*EHH, nullptr);

        // fused attention -> g_vals
        flash_kernel<<<dim3(4, BHH), 256, FLASH_WORDS*4>>>();

        // o = vals @ o_W + o_b
        gemm_kernel<EPI_BIAS><<<dim3(EHH/BN, TOK/BM), 256>>>(
            pvals, EHH, o_W + (size_t)i*EHH*EHH, EHH,
            po, EHH, EHH, o_b + (size_t)i*EHH, nullptr);

        // out1 = x + o @ out_W + out_b
        gemm_kernel<EPI_BIAS_ADD><<<dim3(EE/BN, TOK/BM), 256>>>(
            po, EHH, out_W + (size_t)i*EHH*EE, EE,
            pout1, EE, EHH, out_b + (size_t)i*EE, px);

        ln_kernel<<<TOK, EE>>>(pout1, nullptr, g, bta, pxn);

        // out2 = mish(xn @ ffn_W + ffn_b)
        gemm_kernel<EPI_MISH><<<dim3(EE/BN, TOK/BM), 256>>>(
            pxn, EE, ffn_W + (size_t)i*EE*EE, EE,
            pout2, EE, EE, ffn_b + (size_t)i*EE, nullptr);

        ln_kernel<<<TOK, EE>>>(pout1, pout2, g, bta, px);
    }

    pool_head_kernel<<<Bb, EE>>>(ln2_g, ln2_b, head_W, head_b, out);
}

// round 11
// speedup vs baseline: 2.6339x; 1.1049x over previous
#include <cuda_runtime.h>
#include <cuda_bf16.h>
#include <math.h>
#include <stdint.h>

// ---------------- problem constants ----------------
#define Bb   32
#define SEQ  512
#define EE   128
#define HH   8
#define EHH  1024
#define LL   3
#define TOK  (Bb*SEQ)      // 16384 tokens
#define BHH  (Bb*HH)       // 256 (b,h) pairs
#define KF   101
#define ADIM 200
#define SCALE 0.08838834764831845f

// ---------------- device scratch ----------------
__device__ float g_x    [(size_t)TOK*EE];
__device__ float g_xinit[(size_t)TOK*EE];
__device__ float g_out1 [(size_t)TOK*EE];
__device__ float g_out2 [(size_t)TOK*EE];
__device__ float g_w    [TOK];
__device__ float g_v    [(size_t)BHH*SEQ*EE];

// packed bf16 hi/lo activation planes ([rows][K/2] uint32 words)
__device__ uint32_t g_xnh [(size_t)TOK*64],  g_xnl [(size_t)TOK*64];
__device__ uint32_t g_qh  [(size_t)BHH*SEQ*64], g_ql[(size_t)BHH*SEQ*64];
__device__ uint32_t g_kh  [(size_t)BHH*SEQ*64], g_kl[(size_t)BHH*SEQ*64];
__device__ uint32_t g_valsh[(size_t)TOK*512], g_valsl[(size_t)TOK*512];
__device__ uint32_t g_oh  [(size_t)TOK*512],  g_ol  [(size_t)TOK*512];

// packed weight planes ([N][K/2], per layer)
__device__ uint32_t g_Wqkvh[(size_t)LL*3072*64],  g_Wqkvl[(size_t)LL*3072*64];
__device__ uint32_t g_Woh  [(size_t)LL*1024*512], g_Wol  [(size_t)LL*1024*512];
__device__ uint32_t g_Wouth[(size_t)LL*128*512],  g_Woutl[(size_t)LL*128*512];
__device__ uint32_t g_Wffnh[(size_t)LL*128*64],   g_Wffnl[(size_t)LL*128*64];

// ---------------- helpers ----------------
__device__ __forceinline__ float blkSum128(float v, float* sm) {
    #pragma unroll
    for (int o = 16; o > 0; o >>= 1) v += __shfl_xor_sync(0xffffffffu, v, o);
    int w = threadIdx.x >> 5;
    if ((threadIdx.x & 31) == 0) sm[w] = v;
    __syncthreads();
    float r = sm[0] + sm[1] + sm[2] + sm[3];
    __syncthreads();
    return r;
}

__device__ __forceinline__ void bsplit2(float x, float y, uint32_t& hi, uint32_t& lo) {
    __nv_bfloat16 xh = __float2bfloat16(x);
    __nv_bfloat16 yh = __float2bfloat16(y);
    float xr = x - __bfloat162float(xh);
    float yr = y - __bfloat162float(yh);
    __nv_bfloat162 h2 = __halves2bfloat162(xh, yh);
    __nv_bfloat162 l2 = __halves2bfloat162(__float2bfloat16(xr), __float2bfloat16(yr));
    hi = *reinterpret_cast<uint32_t*>(&h2);
    lo = *reinterpret_cast<uint32_t*>(&l2);
}

__device__ __forceinline__ void mma_bf16(float* d, const uint32_t* a,
                                         uint32_t b0, uint32_t b1) {
    asm volatile(
        "mma.sync.aligned.m16n8k16.row.col.f32.bf16.bf16.f32 "
        "{%0,%1,%2,%3}, {%4,%5,%6,%7}, {%8,%9}, {%0,%1,%2,%3};\n"
        : "+f"(d[0]), "+f"(d[1]), "+f"(d[2]), "+f"(d[3])
        : "r"(a[0]), "r"(a[1]), "r"(a[2]), "r"(a[3]), "r"(b0), "r"(b1));
}

__device__ __forceinline__ void cp16(uint32_t* sdst, const uint32_t* gsrc) {
    uint32_t s = (uint32_t)__cvta_generic_to_shared(sdst);
    asm volatile("cp.async.ca.shared.global [%0], [%1], 16;" :: "r"(s), "l"(gsrc));
}

// ---------------- weight split: W[K][N] float -> planes [N][K/2] ----------------
__global__ void split_weights_kernel(const float* __restrict__ W,
                                     uint32_t* __restrict__ oh,
                                     uint32_t* __restrict__ ol,
                                     int K, int N) {
    int idx = blockIdx.x*256 + threadIdx.x;
    int kw = K >> 1;
    if (idx >= N*kw) return;
    int n = idx % N, kp = idx / N;
    float w0 = W[(size_t)(2*kp)*N + n];
    float w1 = W[(size_t)(2*kp+1)*N + n];
    uint32_t hi, lo; bsplit2(w0, w1, hi, lo);
    oh[(size_t)n*kw + kp] = hi;
    ol[(size_t)n*kw + kp] = lo;
}

// ---------------- embed ----------------
__global__ void embed_kernel(const float* __restrict__ str_fea,
                             const int*   __restrict__ comp_fea,
                             const float* __restrict__ atom_table,
                             const float* __restrict__ comp_W,
                             const float* __restrict__ comp_b,
                             const float* __restrict__ pdd_W,
                             const float* __restrict__ pdd_b) {
    int t = blockIdx.x;
    int e = threadIdx.x;
    __shared__ float sa[ADIM];
    __shared__ float ss[KF-1];
    const float* sf = str_fea + (size_t)t*KF;
    int idx = comp_fea[t];
    const float* at = atom_table + (size_t)idx*ADIM;
    for (int j = e; j < ADIM; j += EE) sa[j] = at[j];
    for (int j = e; j < KF-1; j += EE) ss[j] = sf[1+j];
    if (e == 0) g_w[t] = sf[0];
    __syncthreads();
    float acc = comp_b[e] + pdd_b[e];
    #pragma unroll 4
    for (int a = 0; a < ADIM; a++) acc = fmaf(sa[a], comp_W[a*EE + e], acc);
    #pragma unroll 4
    for (int j = 0; j < KF-1; j++) acc = fmaf(ss[j], pdd_W[j*EE + e], acc);
    g_x[(size_t)t*EE + e]     = acc;
    g_xinit[(size_t)t*EE + e] = acc;
}

// ---------------- layernorm over E=128; PACKED=1 -> bf16 hi/lo planes ----------------
template<int PACKED>
__global__ void ln_kernel(const float* __restrict__ src1,
                          const float* __restrict__ src2,
                          const float* __restrict__ gam,
                          const float* __restrict__ bet,
                          float* __restrict__ dstf,
                          uint32_t* __restrict__ dsth,
                          uint32_t* __restrict__ dstl) {
    __shared__ float sm[4];
    int t = blockIdx.x, e = threadIdx.x;
    size_t off = (size_t)t*EE + e;
    float v = src1[off];
    if (src2) v += src2[off];
    float m = blkSum128(v, sm) * (1.f/EE);
    float d = v - m;
    float var = blkSum128(d*d, sm) * (1.f/EE);
    float r = d * rsqrtf(var + 1e-5f) * gam[e] + bet[e];
    if (PACKED) {
        float r2 = __shfl_down_sync(0xffffffffu, r, 1);
        if ((e & 1) == 0) {
            uint32_t hi, lo; bsplit2(r, r2, hi, lo);
            dsth[(size_t)t*64 + (e >> 1)] = hi;
            dstl[(size_t)t*64 + (e >> 1)] = lo;
        }
    } else {
        dstf[off] = r;
    }
}

// ---------------- pre-split bf16 GEMM (3-mma), cp.async double-buffered ----------------
// Block 128x128x32, 256 threads, warps 4(m) x 2(n), warp tile 32x64.
#define BM 128
#define BN 128
#define GP 20   // smem row pitch in words (16 data + 4 pad), 16B-aligned rows
#define PL 2560 // plane size in words: 128*GP

enum { EPI_BIAS_PACK=0, EPI_BIAS_ADD=1, EPI_MISH=2, EPI_QKV=3 };

template<int EPI>
__global__ __launch_bounds__(256, 2)
void gemm_kernel(const uint32_t* __restrict__ Ah_g, const uint32_t* __restrict__ Al_g, int lda,
                 const uint32_t* __restrict__ Bh_g, const uint32_t* __restrict__ Bl_g, int ldb,
                 float* __restrict__ C, int ldc,
                 uint32_t* __restrict__ Ch, uint32_t* __restrict__ Cl, int ldcw,
                 int K,
                 const float* __restrict__ bias,
                 const float* __restrict__ addend) {
    extern __shared__ uint32_t smx[];   // 2 stages x 4 planes x 2560 words = 80KB
    int bm = blockIdx.y * BM, bn = blockIdx.x * BN;

    int tid  = threadIdx.x;
    int lane = tid & 31;
    int wid  = tid >> 5;
    int warpM = wid & 3;
    int warpN = wid >> 2;
    int g  = lane >> 2;
    int tg = lane & 3;

    float d[2][8][4];
    #pragma unroll
    for (int mt=0; mt<2; mt++)
        #pragma unroll
        for (int nt=0; nt<8; nt++)
            #pragma unroll
            for (int c=0; c<4; c++) d[mt][nt][c] = 0.f;

    int nIter = K >> 5;   // BK = 32 floats = 16 words

    // ---- prefetch stage 0 ----
    {
        uint32_t* s = smx;
        #pragma unroll
        for (int i = 0; i < 2; i++) {
            int c = i*256 + tid;            // 0..511
            int row = c >> 2, q = (c & 3)*4;
            cp16(&s[0*PL + row*GP + q], Ah_g + (size_t)(bm+row)*lda + q);
            cp16(&s[1*PL + row*GP + q], Al_g + (size_t)(bm+row)*lda + q);
            cp16(&s[2*PL + row*GP + q], Bh_g + (size_t)(bn+row)*ldb + q);
            cp16(&s[3*PL + row*GP + q], Bl_g + (size_t)(bn+row)*ldb + q);
        }
    }
    asm volatile("cp.async.commit_group;" ::: "memory");

    for (int it = 0; it < nIter; it++) {
        asm volatile("cp.async.wait_group 0;" ::: "memory");
        __syncthreads();
        if (it + 1 < nIter) {
            uint32_t* s = smx + ((it+1)&1)*4*PL;
            int kw = (it+1)*16;
            #pragma unroll
            for (int i = 0; i < 2; i++) {
                int c = i*256 + tid;
                int row = c >> 2, q = (c & 3)*4;
                cp16(&s[0*PL + row*GP + q], Ah_g + (size_t)(bm+row)*lda + kw + q);
                cp16(&s[1*PL + row*GP + q], Al_g + (size_t)(bm+row)*lda + kw + q);
                cp16(&s[2*PL + row*GP + q], Bh_g + (size_t)(bn+row)*ldb + kw + q);
                cp16(&s[3*PL + row*GP + q], Bl_g + (size_t)(bn+row)*ldb + kw + q);
            }
            asm volatile("cp.async.commit_group;" ::: "memory");
        }

        const uint32_t* Ah = smx + (it&1)*4*PL;
        const uint32_t* Al = Ah + PL;
        const uint32_t* Bh = Al + PL;
        const uint32_t* Bl = Bh + PL;

        #pragma unroll
        for (int js = 0; js < 2; js++) {
            int kb = js*8 + tg;
            uint32_t ah[2][4], al[2][4];
            #pragma unroll
            for (int mt = 0; mt < 2; mt++) {
                int m0 = warpM*32 + mt*16 + g;
                ah[mt][0] = Ah[m0*GP + kb];       al[mt][0] = Al[m0*GP + kb];
                ah[mt][1] = Ah[(m0+8)*GP + kb];   al[mt][1] = Al[(m0+8)*GP + kb];
                ah[mt][2] = Ah[m0*GP + kb+4];     al[mt][2] = Al[m0*GP + kb+4];
                ah[mt][3] = Ah[(m0+8)*GP + kb+4]; al[mt][3] = Al[(m0+8)*GP + kb+4];
            }
            #pragma unroll
            for (int nt = 0; nt < 8; nt++) {
                int n0 = warpN*64 + nt*8 + g;
                uint32_t bh0 = Bh[n0*GP + kb], bh1 = Bh[n0*GP + kb+4];
                uint32_t bl0 = Bl[n0*GP + kb], bl1 = Bl[n0*GP + kb+4];
                #pragma unroll
                for (int mt = 0; mt < 2; mt++) {
                    mma_bf16(d[mt][nt], ah[mt], bh0, bh1);
                    mma_bf16(d[mt][nt], ah[mt], bl0, bl1);
                    mma_bf16(d[mt][nt], al[mt], bh0, bh1);
                }
            }
        }
    }

    // ---- epilogue ----
    #pragma unroll
    for (int mt = 0; mt < 2; mt++) {
        #pragma unroll
        for (int nt = 0; nt < 8; nt++) {
            #pragma unroll
            for (int half = 0; half < 2; half++) {
                int m = bm + warpM*32 + mt*16 + g + half*8;
                int n = bn + warpN*64 + nt*8 + 2*tg;
                float v0 = d[mt][nt][half*2 + 0];
                float v1 = d[mt][nt][half*2 + 1];
                if (EPI == EPI_BIAS_PACK) {
                    uint32_t hi, lo;
                    bsplit2(v0 + bias[n], v1 + bias[n+1], hi, lo);
                    Ch[(size_t)m*ldcw + (n >> 1)] = hi;
                    Cl[(size_t)m*ldcw + (n >> 1)] = lo;
                } else if (EPI == EPI_BIAS_ADD) {
                    const float2 ad = *(const float2*)&addend[(size_t)m*ldc + n];
                    float2 r = make_float2(v0 + bias[n] + ad.x, v1 + bias[n+1] + ad.y);
                    *(float2*)&C[(size_t)m*ldc + n] = r;
                } else if (EPI == EPI_MISH) {
                    float x0 = v0 + bias[n],  x1 = v1 + bias[n+1];
                    float s0 = (x0 > 20.f) ? x0 : log1pf(expf(x0));
                    float s1 = (x1 > 20.f) ? x1 : log1pf(expf(x1));
                    float2 r = make_float2(x0 * tanhf(s0), x1 * tanhf(s1));
                    *(float2*)&C[(size_t)m*ldc + n] = r;
                } else { // EPI_QKV
                    int b = m >> 9, tok = m & 511;
                    int hh = n / 384, rem = n % 384;
                    int rr = rem >> 7, dd = rem & 127;
                    size_t bhrow = ((size_t)(b*HH + hh)*SEQ + tok);
                    float x0 = v0 + bias[n], x1 = v1 + bias[n+1];
                    if (rr == 0) {
                        uint32_t hi, lo; bsplit2(x0*SCALE, x1*SCALE, hi, lo);
                        g_qh[bhrow*64 + (dd>>1)] = hi;
                        g_ql[bhrow*64 + (dd>>1)] = lo;
                    } else if (rr == 1) {
                        uint32_t hi, lo; bsplit2(x0, x1, hi, lo);
                        g_kh[bhrow*64 + (dd>>1)] = hi;
                        g_kl[bhrow*64 + (dd>>1)] = lo;
                    } else {
                        *(float2*)&g_v[bhrow*EE + dd] = make_float2(x0, x1);
                    }
                }
            }
        }
    }
}

// ---------------- fused flash attention ----------------
// grid (4 qtiles, 256 bh), 256 threads = 8 warps, each warp owns 16 q-rows.
#define QP 68   // pitch for [row][kp(d)=64] tiles
#define VP 36   // pitch for [d][kp(key)=32] tiles
#define NKT (SEQ/64)   // 8 key tiles

#define OFF_QH 0
#define OFF_QL (OFF_QH + 128*QP)
#define OFF_KH (OFF_QL + 128*QP)
#define OFF_KL (OFF_KH + 64*QP)
#define OFF_VH (OFF_KL + 64*QP)
#define OFF_VL (OFF_VH + 128*VP)
#define OFF_WS (OFF_VL + 128*VP)
#define FLASH_WORDS (OFF_WS + 64)

__global__ __launch_bounds__(256, 1)
void flash_kernel() {
    extern __shared__ uint32_t smx[];
    uint32_t* Qh = smx + OFF_QH;
    uint32_t* Ql = smx + OFF_QL;
    uint32_t* Kh = smx + OFF_KH;
    uint32_t* Kl = smx + OFF_KL;
    uint32_t* Vh = smx + OFF_VH;
    uint32_t* Vl = smx + OFF_VL;
    float*    ws = (float*)(smx + OFF_WS);

    int qt = blockIdx.x, bh = blockIdx.y;
    int b = bh >> 3, h = bh & 7;
    int tid = threadIdx.x;
    int lane = tid & 31;
    int wid = tid >> 5;
    int g = lane >> 2, tg = lane & 3;

    // Q tile: direct copy of pre-split planes
    const uint32_t* Qgh = g_qh + ((size_t)bh*SEQ + qt*128)*64;
    const uint32_t* Qgl = g_ql + ((size_t)bh*SEQ + qt*128)*64;
    #pragma unroll
    for (int i = 0; i < 8; i++) {
        int c = i*256 + tid;               // 0..2047
        int row = c >> 4, q = (c & 15)*4;
        *(uint4*)&Qh[row*QP + q] = *(const uint4*)&Qgh[row*64 + q];
        *(uint4*)&Ql[row*QP + q] = *(const uint4*)&Qgl[row*64 + q];
    }

    int rowg = qt*128 + wid*16 + g;
    bool mq0 = g_w[b*SEQ + rowg]     > 0.f;
    bool mq1 = g_w[b*SEQ + rowg + 8] > 0.f;

    float m_run[2] = {-9.0e15f, -9.0e15f};
    float l_run[2] = {0.f, 0.f};
    float o[16][4];
    #pragma unroll
    for (int dt = 0; dt < 16; dt++)
        #pragma unroll
        for (int c = 0; c < 4; c++) o[dt][c] = 0.f;

    for (int kt = 0; kt < NKT; kt++) {
        __syncthreads();
        if (tid < 64) ws[tid] = g_w[b*SEQ + kt*64 + tid];
        // K tile: direct copy
        const uint32_t* Kgh = g_kh + ((size_t)bh*SEQ + kt*64)*64;
        const uint32_t* Kgl = g_kl + ((size_t)bh*SEQ + kt*64)*64;
        #pragma unroll
        for (int i = 0; i < 4; i++) {
            int c = i*256 + tid;           // 0..1023
            int row = c >> 4, q = (c & 15)*4;
            *(uint4*)&Kh[row*QP + q] = *(const uint4*)&Kgh[row*64 + q];
            *(uint4*)&Kl[row*QP + q] = *(const uint4*)&Kgl[row*64 + q];
        }
        // V tile: float -> split transposed [d][key-pair]
        const float* Vg = g_v + ((size_t)bh*SEQ + kt*64)*EE;
        #pragma unroll
        for (int i = 0; i < 4; i++) {
            int e = i*256 + tid;
            int d4 = e & 31, kp = e >> 5;
            const float4 ve = *(const float4*)&Vg[(2*kp  )*EE + 4*d4];
            const float4 vo = *(const float4*)&Vg[(2*kp+1)*EE + 4*d4];
            bsplit2(ve.x, vo.x, Vh[(4*d4+0)*VP + kp], Vl[(4*d4+0)*VP + kp]);
            bsplit2(ve.y, vo.y, Vh[(4*d4+1)*VP + kp], Vl[(4*d4+1)*VP + kp]);
            bsplit2(ve.z, vo.z, Vh[(4*d4+2)*VP + kp], Vl[(4*d4+2)*VP + kp]);
            bsplit2(ve.w, vo.w, Vh[(4*d4+3)*VP + kp], Vl[(4*d4+3)*VP + kp]);
        }
        __syncthreads();

        // ---- S = Q @ K^T ----
        float s[8][4];
        #pragma unroll
        for (int nt=0; nt<8; nt++)
            #pragma unroll
            for (int c=0; c<4; c++) s[nt][c] = 0.f;

        int m0 = wid*16 + g;
        #pragma unroll
        for (int ks = 0; ks < 8; ks++) {
            int kb = ks*8 + tg;
            uint32_t ah[4], al[4];
            ah[0] = Qh[m0*QP + kb];       al[0] = Ql[m0*QP + kb];
            ah[1] = Qh[(m0+8)*QP + kb];   al[1] = Ql[(m0+8)*QP + kb];
            ah[2] = Qh[m0*QP + kb+4];     al[2] = Ql[m0*QP + kb+4];
            ah[3] = Qh[(m0+8)*QP + kb+4]; al[3] = Ql[(m0+8)*QP + kb+4];
            #pragma unroll
            for (int nt = 0; nt < 8; nt++) {
                int n0 = nt*8 + g;
                uint32_t bh0 = Kh[n0*QP + kb], bh1 = Kh[n0*QP + kb+4];
                uint32_t bl0 = Kl[n0*QP + kb], bl1 = Kl[n0*QP + kb+4];
                mma_bf16(s[nt], ah, bh0, bh1);
                mma_bf16(s[nt], ah, bl0, bl1);
                mma_bf16(s[nt], al, bh0, bh1);
            }
        }

        // ---- mask + online softmax ----
        float tmax[2] = {-9.0e15f, -9.0e15f};
        #pragma unroll
        for (int nt = 0; nt < 8; nt++) {
            int col0 = nt*8 + 2*tg;
            #pragma unroll
            for (int c = 0; c < 4; c++) {
                bool mk = ws[col0 + (c & 1)] > 0.f;
                bool mr = (c < 2) ? mq0 : mq1;
                float v = (mk && mr) ? s[nt][c] : -9.0e15f;
                s[nt][c] = v;
                tmax[c >> 1] = fmaxf(tmax[c >> 1], v);
            }
        }
        #pragma unroll
        for (int off = 1; off <= 2; off <<= 1) {
            tmax[0] = fmaxf(tmax[0], __shfl_xor_sync(0xffffffffu, tmax[0], off));
            tmax[1] = fmaxf(tmax[1], __shfl_xor_sync(0xffffffffu, tmax[1], off));
        }
        float nm0 = fmaxf(m_run[0], tmax[0]);
        float nm1 = fmaxf(m_run[1], tmax[1]);
        float a0 = __expf(m_run[0] - nm0);
        float a1 = __expf(m_run[1] - nm1);
        float rs[2] = {0.f, 0.f};
        #pragma unroll
        for (int nt = 0; nt < 8; nt++) {
            int col0 = nt*8 + 2*tg;
            #pragma unroll
            for (int c = 0; c < 4; c++) {
                float nm = (c < 2) ? nm0 : nm1;
                float p = ws[col0 + (c & 1)] * __expf(s[nt][c] - nm);
                s[nt][c] = p;
                rs[c >> 1] += p;
            }
        }
        #pragma unroll
        for (int off = 1; off <= 2; off <<= 1) {
            rs[0] += __shfl_xor_sync(0xffffffffu, rs[0], off);
            rs[1] += __shfl_xor_sync(0xffffffffu, rs[1], off);
        }
        l_run[0] = a0*l_run[0] + rs[0];
        l_run[1] = a1*l_run[1] + rs[1];
        m_run[0] = nm0; m_run[1] = nm1;
        #pragma unroll
        for (int dt = 0; dt < 16; dt++) {
            o[dt][0] *= a0; o[dt][1] *= a0;
            o[dt][2] *= a1; o[dt][3] *= a1;
        }

        // ---- O += P @ V ----
        #pragma unroll
        for (int j = 0; j < 4; j++) {
            uint32_t pah[4], pal[4];
            bsplit2(s[2*j  ][0], s[2*j  ][1], pah[0], pal[0]);
            bsplit2(s[2*j  ][2], s[2*j  ][3], pah[1], pal[1]);
            bsplit2(s[2*j+1][0], s[2*j+1][1], pah[2], pal[2]);
            bsplit2(s[2*j+1][2], s[2*j+1][3], pah[3], pal[3]);
            int kb = j*8 + tg;
            #pragma unroll
            for (int dt = 0; dt < 16; dt++) {
                int n0 = dt*8 + g;
                uint32_t vh0 = Vh[n0*VP + kb], vh1 = Vh[n0*VP + kb+4];
                uint32_t vl0 = Vl[n0*VP + kb], vl1 = Vl[n0*VP + kb+4];
                mma_bf16(o[dt], pah, vh0, vh1);
                mma_bf16(o[dt], pah, vl0, vl1);
                mma_bf16(o[dt], pal, vh0, vh1);
            }
        }
    }

    // ---- normalize + store split vals planes ----
    float inv0 = 1.f / l_run[0];
    float inv1 = 1.f / l_run[1];
    size_t r0 = (size_t)(b*SEQ) + qt*128 + wid*16 + g;
    size_t r1 = r0 + 8;
    #pragma unroll
    for (int dt = 0; dt < 16; dt++) {
        int w = h*64 + dt*4 + tg;
        uint32_t hi, lo;
        bsplit2(o[dt][0]*inv0, o[dt][1]*inv0, hi, lo);
        g_valsh[r0*512 + w] = hi; g_valsl[r0*512 + w] = lo;
        bsplit2(o[dt][2]*inv1, o[dt][3]*inv1, hi, lo);
        g_valsh[r1*512 + w] = hi; g_valsl[r1*512 + w] = lo;
    }
}

// ---------------- final: weighted pool + LN + head ----------------
__global__ void pool_head_kernel(const float* __restrict__ ln2_g,
                                 const float* __restrict__ ln2_b,
                                 const float* __restrict__ head_W,
                                 const float* __restrict__ head_b,
                                 float* __restrict__ out) {
    __shared__ float sm[4];
    int b = blockIdx.x, e = threadIdx.x;
    const float* xb  = g_x     + (size_t)b*SEQ*EE;
    const float* xib = g_xinit + (size_t)b*SEQ*EE;
    float s = 0.f;
    for (int n = 0; n < SEQ; n++)
        s = fmaf(g_w[b*SEQ + n], xb[n*EE + e] + xib[n*EE + e], s);
    float m = blkSum128(s, sm) * (1.f/EE);
    float d = s - m;
    float var = blkSum128(d*d, sm) * (1.f/EE);
    float p = d * rsqrtf(var + 1e-5f) * ln2_g[e] + ln2_b[e];
    float dot = blkSum128(p * head_W[e], sm);
    if (e == 0) out[b] = dot + head_b[0];
}

// ---------------- host launch ----------------
#define GEMM_SMEM (2*4*PL*4)

extern "C" void kernel_launch(void* const* d_in, const int* in_sizes, int n_in,
                              void* d_out, int out_size) {
    (void)in_sizes; (void)n_in; (void)out_size;
    const float* str_fea   = (const float*)d_in[0];
    const int*   comp_fea  = (const int*)  d_in[1];
    const float* atom_table= (const float*)d_in[3];
    const float* comp_W    = (const float*)d_in[4];
    const float* comp_b    = (const float*)d_in[5];
    const float* pdd_W     = (const float*)d_in[6];
    const float* pdd_b     = (const float*)d_in[7];
    const float* enc_ln_g  = (const float*)d_in[8];
    const float* enc_ln_b  = (const float*)d_in[9];
    const float* qkv_W     = (const float*)d_in[10];
    const float* qkv_b     = (const float*)d_in[11];
    const float* o_W       = (const float*)d_in[12];
    const float* o_b       = (const float*)d_in[13];
    const float* out_W     = (const float*)d_in[14];
    const float* out_b     = (const float*)d_in[15];
    const float* ffn_W     = (const float*)d_in[16];
    const float* ffn_b     = (const float*)d_in[17];
    const float* ln2_g     = (const float*)d_in[18];
    const float* ln2_b     = (const float*)d_in[19];
    const float* head_W    = (const float*)d_in[20];
    const float* head_b    = (const float*)d_in[21];
    float* out = (float*)d_out;

    void* p;
    cudaGetSymbolAddress(&p, g_x);      float* px    = (float*)p;
    cudaGetSymbolAddress(&p, g_out1);   float* pout1 = (float*)p;
    cudaGetSymbolAddress(&p, g_out2);   float* pout2 = (float*)p;
    cudaGetSymbolAddress(&p, g_xnh);    uint32_t* pxnh = (uint32_t*)p;
    cudaGetSymbolAddress(&p, g_xnl);    uint32_t* pxnl = (uint32_t*)p;
    cudaGetSymbolAddress(&p, g_valsh);  uint32_t* pvalsh = (uint32_t*)p;
    cudaGetSymbolAddress(&p, g_valsl);  uint32_t* pvalsl = (uint32_t*)p;
    cudaGetSymbolAddress(&p, g_oh);     uint32_t* poh = (uint32_t*)p;
    cudaGetSymbolAddress(&p, g_ol);     uint32_t* pol = (uint32_t*)p;
    cudaGetSymbolAddress(&p, g_Wqkvh);  uint32_t* pWqkvh = (uint32_t*)p;
    cudaGetSymbolAddress(&p, g_Wqkvl);  uint32_t* pWqkvl = (uint32_t*)p;
    cudaGetSymbolAddress(&p, g_Woh);    uint32_t* pWoh = (uint32_t*)p;
    cudaGetSymbolAddress(&p, g_Wol);    uint32_t* pWol = (uint32_t*)p;
    cudaGetSymbolAddress(&p, g_Wouth);  uint32_t* pWouth = (uint32_t*)p;
    cudaGetSymbolAddress(&p, g_Woutl);  uint32_t* pWoutl = (uint32_t*)p;
    cudaGetSymbolAddress(&p, g_Wffnh);  uint32_t* pWffnh = (uint32_t*)p;
    cudaGetSymbolAddress(&p, g_Wffnl);  uint32_t* pWffnl = (uint32_t*)p;

    static bool attr_done = false;
    if (!attr_done) {
        cudaFuncSetAttribute(flash_kernel,
            cudaFuncAttributeMaxDynamicSharedMemorySize, FLASH_WORDS * 4);
        cudaFuncSetAttribute(gemm_kernel<EPI_BIAS_PACK>,
            cudaFuncAttributeMaxDynamicSharedMemorySize, GEMM_SMEM);
        cudaFuncSetAttribute(gemm_kernel<EPI_BIAS_ADD>,
            cudaFuncAttributeMaxDynamicSharedMemorySize, GEMM_SMEM);
        cudaFuncSetAttribute(gemm_kernel<EPI_MISH>,
            cudaFuncAttributeMaxDynamicSharedMemorySize, GEMM_SMEM);
        cudaFuncSetAttribute(gemm_kernel<EPI_QKV>,
            cudaFuncAttributeMaxDynamicSharedMemorySize, GEMM_SMEM);
        attr_done = true;
    }

    // ---- pre-split all weights into [N][K/2] bf16 hi/lo planes ----
    for (int i = 0; i < LL; i++) {
        split_weights_kernel<<<(3072*64 + 255)/256, 256>>>(
            qkv_W + (size_t)i*EE*3*EHH, pWqkvh + (size_t)i*3072*64,
            pWqkvl + (size_t)i*3072*64, EE, 3*EHH);
        split_weights_kernel<<<(1024*512 + 255)/256, 256>>>(
            o_W + (size_t)i*EHH*EHH, pWoh + (size_t)i*1024*512,
            pWol + (size_t)i*1024*512, EHH, EHH);
        split_weights_kernel<<<(128*512 + 255)/256, 256>>>(
            out_W + (size_t)i*EHH*EE, pWouth + (size_t)i*128*512,
            pWoutl + (size_t)i*128*512, EHH, EE);
        split_weights_kernel<<<(128*64 + 255)/256, 256>>>(
            ffn_W + (size_t)i*EE*EE, pWffnh + (size_t)i*128*64,
            pWffnl + (size_t)i*128*64, EE, EE);
    }

    embed_kernel<<<TOK, EE>>>(str_fea, comp_fea, atom_table,
                              comp_W, comp_b, pdd_W, pdd_b);

    for (int i = 0; i < LL; i++) {
        const float* g = enc_ln_g + i*EE;
        const float* bta = enc_ln_b + i*EE;

        // xn = LN(x) -> packed planes
        ln_kernel<1><<<TOK, EE>>>(px, nullptr, g, bta, nullptr, pxnh, pxnl);

        // qkv projection -> scatter packed q (scaled) / packed k / float v
        gemm_kernel<EPI_QKV><<<dim3(3*EHH/BN, TOK/BM), 256, GEMM_SMEM>>>(
            pxnh, pxnl, 64,
            pWqkvh + (size_t)i*3072*64, pWqkvl + (size_t)i*3072*64, 64,
            nullptr, 0, nullptr, nullptr, 0, EE,
            qkv_b + (size_t)i*3*EHH, nullptr);

        // fused attention -> packed vals planes
        flash_kernel<<<dim3(4, BHH), 256, FLASH_WORDS*4>>>();

        // o = vals @ o_W + o_b -> packed o planes
        gemm_kernel<EPI_BIAS_PACK><<<dim3(EHH/BN, TOK/BM), 256, GEMM_SMEM>>>(
            pvalsh, pvalsl, 512,
            pWoh + (size_t)i*1024*512, pWol + (size_t)i*1024*512, 512,
            nullptr, 0, poh, pol, 512, EHH,
            o_b + (size_t)i*EHH, nullptr);

        // out1 = x + o @ out_W + out_b (float)
        gemm_kernel<EPI_BIAS_ADD><<<dim3(EE/BN, TOK/BM), 256, GEMM_SMEM>>>(
            poh, pol, 512,
            pWouth + (size_t)i*128*512, pWoutl + (size_t)i*128*512, 512,
            pout1, EE, nullptr, nullptr, 0, EHH,
            out_b + (size_t)i*EE, px);

        // xn = LN(out1) -> packed planes
        ln_kernel<1><<<TOK, EE>>>(pout1, nullptr, g, bta, nullptr, pxnh, pxnl);

        // out2 = mish(xn @ ffn_W + ffn_b) (float)
        gemm_kernel<EPI_MISH><<<dim3(EE/BN, TOK/BM), 256, GEMM_SMEM>>>(
            pxnh, pxnl, 64,
            pWffnh + (size_t)i*128*64, pWffnl + (size_t)i*128*64, 64,
            pout2, EE, nullptr, nullptr, 0, EE,
            ffn_b + (size_t)i*EE, nullptr);

        // x = LN(out1 + out2) (float)
        ln_kernel<0><<<TOK, EE>>>(pout1, pout2, g, bta, px, nullptr, nullptr);
    }

    pool_head_kernel<<<Bb, EE>>>(ln2_g, ln2_b, head_W, head_b, out);
}

// round 13
// speedup vs baseline: 2.8136x; 1.0682x over previous
#include <cuda_runtime.h>
#include <cuda_bf16.h>
#include <math.h>
#include <stdint.h>

// ---------------- problem constants ----------------
#define Bb   32
#define SEQ  512
#define EE   128
#define HH   8
#define EHH  1024
#define LL   3
#define TOK  (Bb*SEQ)      // 16384 tokens
#define BHH  (Bb*HH)       // 256 (b,h) pairs
#define KF   101
#define ADIM 200
#define SCALE 0.08838834764831845f

// ---------------- device scratch ----------------
__device__ float g_x    [(size_t)TOK*EE];
__device__ float g_xinit[(size_t)TOK*EE];
__device__ float g_out1 [(size_t)TOK*EE];
__device__ float g_out2 [(size_t)TOK*EE];
__device__ float g_w    [TOK];
__device__ float g_v    [(size_t)BHH*SEQ*EE];

// packed bf16 hi/lo activation planes ([rows][K/2] uint32 words)
__device__ uint32_t g_xnh [(size_t)TOK*64],  g_xnl [(size_t)TOK*64];
__device__ uint32_t g_qh  [(size_t)BHH*SEQ*64], g_ql[(size_t)BHH*SEQ*64];
__device__ uint32_t g_kh  [(size_t)BHH*SEQ*64], g_kl[(size_t)BHH*SEQ*64];
__device__ uint32_t g_vth [(size_t)BHH*EE*256], g_vtl[(size_t)BHH*EE*256]; // V^T packed [bh][d][tokpair]
__device__ uint32_t g_valsh[(size_t)TOK*512], g_valsl[(size_t)TOK*512];
__device__ uint32_t g_oh  [(size_t)TOK*512],  g_ol  [(size_t)TOK*512];

// packed weight planes ([N][K/2], per layer)
__device__ uint32_t g_Wqkvh[(size_t)LL*3072*64],  g_Wqkvl[(size_t)LL*3072*64];
__device__ uint32_t g_Woh  [(size_t)LL*1024*512], g_Wol  [(size_t)LL*1024*512];
__device__ uint32_t g_Wouth[(size_t)LL*128*512],  g_Woutl[(size_t)LL*128*512];
__device__ uint32_t g_Wffnh[(size_t)LL*128*64],   g_Wffnl[(size_t)LL*128*64];

// ---------------- helpers ----------------
__device__ __forceinline__ float blkSum128(float v, float* sm) {
    #pragma unroll
    for (int o = 16; o > 0; o >>= 1) v += __shfl_xor_sync(0xffffffffu, v, o);
    int w = threadIdx.x >> 5;
    if ((threadIdx.x & 31) == 0) sm[w] = v;
    __syncthreads();
    float r = sm[0] + sm[1] + sm[2] + sm[3];
    __syncthreads();
    return r;
}

__device__ __forceinline__ void bsplit2(float x, float y, uint32_t& hi, uint32_t& lo) {
    __nv_bfloat16 xh = __float2bfloat16(x);
    __nv_bfloat16 yh = __float2bfloat16(y);
    float xr = x - __bfloat162float(xh);
    float yr = y - __bfloat162float(yh);
    __nv_bfloat162 h2 = __halves2bfloat162(xh, yh);
    __nv_bfloat162 l2 = __halves2bfloat162(__float2bfloat16(xr), __float2bfloat16(yr));
    hi = *reinterpret_cast<uint32_t*>(&h2);
    lo = *reinterpret_cast<uint32_t*>(&l2);
}

__device__ __forceinline__ void mma_bf16(float* d, const uint32_t* a,
                                         uint32_t b0, uint32_t b1) {
    asm volatile(
        "mma.sync.aligned.m16n8k16.row.col.f32.bf16.bf16.f32 "
        "{%0,%1,%2,%3}, {%4,%5,%6,%7}, {%8,%9}, {%0,%1,%2,%3};\n"
        : "+f"(d[0]), "+f"(d[1]), "+f"(d[2]), "+f"(d[3])
        : "r"(a[0]), "r"(a[1]), "r"(a[2]), "r"(a[3]), "r"(b0), "r"(b1));
}

__device__ __forceinline__ void cp16(uint32_t* sdst, const uint32_t* gsrc) {
    uint32_t s = (uint32_t)__cvta_generic_to_shared(sdst);
    asm volatile("cp.async.ca.shared.global [%0], [%1], 16;" :: "r"(s), "l"(gsrc));
}

// ---------------- weight split: W[K][N] float -> planes [N][K/2]; y = layer ----------------
__global__ void split_weights_kernel(const float* __restrict__ W,
                                     uint32_t* __restrict__ oh,
                                     uint32_t* __restrict__ ol,
                                     int K, int N) {
    int kw = K >> 1;
    size_t lw = (size_t)N*kw;
    int L = blockIdx.y;
    W  += (size_t)L*K*N;
    oh += (size_t)L*lw;
    ol += (size_t)L*lw;
    int idx = blockIdx.x*256 + threadIdx.x;
    if (idx >= N*kw) return;
    int n = idx % N, kp = idx / N;
    float w0 = W[(size_t)(2*kp)*N + n];
    float w1 = W[(size_t)(2*kp+1)*N + n];
    uint32_t hi, lo; bsplit2(w0, w1, hi, lo);
    oh[(size_t)n*kw + kp] = hi;
    ol[(size_t)n*kw + kp] = lo;
}

// ---------------- embed ----------------
__global__ void embed_kernel(const float* __restrict__ str_fea,
                             const int*   __restrict__ comp_fea,
                             const float* __restrict__ atom_table,
                             const float* __restrict__ comp_W,
                             const float* __restrict__ comp_b,
                             const float* __restrict__ pdd_W,
                             const float* __restrict__ pdd_b) {
    int t = blockIdx.x;
    int e = threadIdx.x;
    __shared__ float sa[ADIM];
    __shared__ float ss[KF-1];
    const float* sf = str_fea + (size_t)t*KF;
    int idx = comp_fea[t];
    const float* at = atom_table + (size_t)idx*ADIM;
    for (int j = e; j < ADIM; j += EE) sa[j] = at[j];
    for (int j = e; j < KF-1; j += EE) ss[j] = sf[1+j];
    if (e == 0) g_w[t] = sf[0];
    __syncthreads();
    float acc = comp_b[e] + pdd_b[e];
    #pragma unroll 4
    for (int a = 0; a < ADIM; a++) acc = fmaf(sa[a], comp_W[a*EE + e], acc);
    #pragma unroll 4
    for (int j = 0; j < KF-1; j++) acc = fmaf(ss[j], pdd_W[j*EE + e], acc);
    g_x[(size_t)t*EE + e]     = acc;
    g_xinit[(size_t)t*EE + e] = acc;
}

// ---------------- warp-per-token layernorm; PACKED=1 -> bf16 hi/lo planes ----------------
template<int PACKED>
__global__ void ln_kernel(const float* __restrict__ src1,
                          const float* __restrict__ src2,
                          const float* __restrict__ gam,
                          const float* __restrict__ bet,
                          float* __restrict__ dstf,
                          uint32_t* __restrict__ dsth,
                          uint32_t* __restrict__ dstl) {
    int warp = threadIdx.x >> 5, lane = threadIdx.x & 31;
    int t = blockIdx.x*4 + warp;
    size_t off = (size_t)t*EE + lane*4;
    float4 v = *(const float4*)&src1[off];
    if (src2) {
        const float4 u = *(const float4*)&src2[off];
        v.x += u.x; v.y += u.y; v.z += u.z; v.w += u.w;
    }
    float s = v.x + v.y + v.z + v.w;
    #pragma unroll
    for (int o = 16; o > 0; o >>= 1) s += __shfl_xor_sync(0xffffffffu, s, o);
    float m = s * (1.f/EE);
    float dx = v.x - m, dy = v.y - m, dz = v.z - m, dw = v.w - m;
    float q = dx*dx + dy*dy + dz*dz + dw*dw;
    #pragma unroll
    for (int o = 16; o > 0; o >>= 1) q += __shfl_xor_sync(0xffffffffu, q, o);
    float rstd = rsqrtf(q * (1.f/EE) + 1e-5f);
    const float4 gv = *(const float4*)&gam[lane*4];
    const float4 bv = *(const float4*)&bet[lane*4];
    float r0 = dx*rstd*gv.x + bv.x;
    float r1 = dy*rstd*gv.y + bv.y;
    float r2 = dz*rstd*gv.z + bv.z;
    float r3 = dw*rstd*gv.w + bv.w;
    if (PACKED) {
        uint32_t h0, l0, h1, l1;
        bsplit2(r0, r1, h0, l0);
        bsplit2(r2, r3, h1, l1);
        *(uint2*)&dsth[(size_t)t*64 + lane*2] = make_uint2(h0, h1);
        *(uint2*)&dstl[(size_t)t*64 + lane*2] = make_uint2(l0, l1);
    } else {
        *(float4*)&dstf[off] = make_float4(r0, r1, r2, r3);
    }
}

// ---------------- V transpose+split: g_v [bh][tok][d] -> packed [bh][d][tokpair] ----------------
__global__ void transpose_v_kernel() {
    __shared__ float sv[64][129];
    int bh = blockIdx.y, t0 = blockIdx.x*64;
    int tid = threadIdx.x;
    const float* Vg = g_v + ((size_t)bh*SEQ + t0)*EE;
    #pragma unroll
    for (int i = 0; i < 8; i++) {
        int c = i*256 + tid;               // 0..2047 float4s
        int tok = c >> 5, q = (c & 31)*4;
        const float4 f = *(const float4*)&Vg[(size_t)tok*EE + q];
        sv[tok][q]   = f.x; sv[tok][q+1] = f.y;
        sv[tok][q+2] = f.z; sv[tok][q+3] = f.w;
    }
    __syncthreads();
    uint32_t* oh = g_vth + (size_t)bh*EE*256 + (t0 >> 1);
    uint32_t* ol = g_vtl + (size_t)bh*EE*256 + (t0 >> 1);
    #pragma unroll
    for (int i = 0; i < 16; i++) {
        int widx = i*256 + tid;            // 0..4095
        int d = widx >> 5, tp = widx & 31;
        uint32_t hi, lo;
        bsplit2(sv[2*tp][d], sv[2*tp+1][d], hi, lo);
        oh[(size_t)d*256 + tp] = hi;
        ol[(size_t)d*256 + tp] = lo;
    }
}

// ---------------- pre-split bf16 GEMM (3-mma), cp.async double-buffered ----------------
#define BM 128
#define BN 128
#define GP 20   // smem row pitch in words
#define PL 2560 // plane size: 128*GP

enum { EPI_BIAS_PACK=0, EPI_BIAS_ADD=1, EPI_MISH=2, EPI_QKV=3 };

template<int EPI>
__global__ __launch_bounds__(256, 2)
void gemm_kernel(const uint32_t* __restrict__ Ah_g, const uint32_t* __restrict__ Al_g, int lda,
                 const uint32_t* __restrict__ Bh_g, const uint32_t* __restrict__ Bl_g, int ldb,
                 float* __restrict__ C, int ldc,
                 uint32_t* __restrict__ Ch, uint32_t* __restrict__ Cl, int ldcw,
                 int K,
                 const float* __restrict__ bias,
                 const float* __restrict__ addend) {
    extern __shared__ uint32_t smx[];
    int bm = blockIdx.y * BM, bn = blockIdx.x * BN;

    int tid  = threadIdx.x;
    int lane = tid & 31;
    int wid  = tid >> 5;
    int warpM = wid & 3;
    int warpN = wid >> 2;
    int g  = lane >> 2;
    int tg = lane & 3;

    float d[2][8][4];
    #pragma unroll
    for (int mt=0; mt<2; mt++)
        #pragma unroll
        for (int nt=0; nt<8; nt++)
            #pragma unroll
            for (int c=0; c<4; c++) d[mt][nt][c] = 0.f;

    int nIter = K >> 5;

    {
        uint32_t* s = smx;
        #pragma unroll
        for (int i = 0; i < 2; i++) {
            int c = i*256 + tid;
            int row = c >> 2, q = (c & 3)*4;
            cp16(&s[0*PL + row*GP + q], Ah_g + (size_t)(bm+row)*lda + q);
            cp16(&s[1*PL + row*GP + q], Al_g + (size_t)(bm+row)*lda + q);
            cp16(&s[2*PL + row*GP + q], Bh_g + (size_t)(bn+row)*ldb + q);
            cp16(&s[3*PL + row*GP + q], Bl_g + (size_t)(bn+row)*ldb + q);
        }
    }
    asm volatile("cp.async.commit_group;" ::: "memory");

    for (int it = 0; it < nIter; it++) {
        asm volatile("cp.async.wait_group 0;" ::: "memory");
        __syncthreads();
        if (it + 1 < nIter) {
            uint32_t* s = smx + ((it+1)&1)*4*PL;
            int kw = (it+1)*16;
            #pragma unroll
            for (int i = 0; i < 2; i++) {
                int c = i*256 + tid;
                int row = c >> 2, q = (c & 3)*4;
                cp16(&s[0*PL + row*GP + q], Ah_g + (size_t)(bm+row)*lda + kw + q);
                cp16(&s[1*PL + row*GP + q], Al_g + (size_t)(bm+row)*lda + kw + q);
                cp16(&s[2*PL + row*GP + q], Bh_g + (size_t)(bn+row)*ldb + kw + q);
                cp16(&s[3*PL + row*GP + q], Bl_g + (size_t)(bn+row)*ldb + kw + q);
            }
            asm volatile("cp.async.commit_group;" ::: "memory");
        }

        const uint32_t* Ah = smx + (it&1)*4*PL;
        const uint32_t* Al = Ah + PL;
        const uint32_t* Bh = Al + PL;
        const uint32_t* Bl = Bh + PL;

        #pragma unroll
        for (int js = 0; js < 2; js++) {
            int kb = js*8 + tg;
            uint32_t ah[2][4], al[2][4];
            #pragma unroll
            for (int mt = 0; mt < 2; mt++) {
                int m0 = warpM*32 + mt*16 + g;
                ah[mt][0] = Ah[m0*GP + kb];       al[mt][0] = Al[m0*GP + kb];
                ah[mt][1] = Ah[(m0+8)*GP + kb];   al[mt][1] = Al[(m0+8)*GP + kb];
                ah[mt][2] = Ah[m0*GP + kb+4];     al[mt][2] = Al[m0*GP + kb+4];
                ah[mt][3] = Ah[(m0+8)*GP + kb+4]; al[mt][3] = Al[(m0+8)*GP + kb+4];
            }
            #pragma unroll
            for (int nt = 0; nt < 8; nt++) {
                int n0 = warpN*64 + nt*8 + g;
                uint32_t bh0 = Bh[n0*GP + kb], bh1 = Bh[n0*GP + kb+4];
                uint32_t bl0 = Bl[n0*GP + kb], bl1 = Bl[n0*GP + kb+4];
                #pragma unroll
                for (int mt = 0; mt < 2; mt++) {
                    mma_bf16(d[mt][nt], ah[mt], bh0, bh1);
                    mma_bf16(d[mt][nt], ah[mt], bl0, bl1);
                    mma_bf16(d[mt][nt], al[mt], bh0, bh1);
                }
            }
        }
    }

    #pragma unroll
    for (int mt = 0; mt < 2; mt++) {
        #pragma unroll
        for (int nt = 0; nt < 8; nt++) {
            #pragma unroll
            for (int half = 0; half < 2; half++) {
                int m = bm + warpM*32 + mt*16 + g + half*8;
                int n = bn + warpN*64 + nt*8 + 2*tg;
                float v0 = d[mt][nt][half*2 + 0];
                float v1 = d[mt][nt][half*2 + 1];
                if (EPI == EPI_BIAS_PACK) {
                    uint32_t hi, lo;
                    bsplit2(v0 + bias[n], v1 + bias[n+1], hi, lo);
                    Ch[(size_t)m*ldcw + (n >> 1)] = hi;
                    Cl[(size_t)m*ldcw + (n >> 1)] = lo;
                } else if (EPI == EPI_BIAS_ADD) {
                    const float2 ad = *(const float2*)&addend[(size_t)m*ldc + n];
                    float2 r = make_float2(v0 + bias[n] + ad.x, v1 + bias[n+1] + ad.y);
                    *(float2*)&C[(size_t)m*ldc + n] = r;
                } else if (EPI == EPI_MISH) {
                    float x0 = v0 + bias[n],  x1 = v1 + bias[n+1];
                    float s0 = (x0 > 20.f) ? x0 : log1pf(expf(x0));
                    float s1 = (x1 > 20.f) ? x1 : log1pf(expf(x1));
                    float2 r = make_float2(x0 * tanhf(s0), x1 * tanhf(s1));
                    *(float2*)&C[(size_t)m*ldc + n] = r;
                } else { // EPI_QKV
                    int b = m >> 9, tok = m & 511;
                    int hh = n / 384, rem = n % 384;
                    int rr = rem >> 7, dd = rem & 127;
                    size_t bhrow = ((size_t)(b*HH + hh)*SEQ + tok);
                    float x0 = v0 + bias[n], x1 = v1 + bias[n+1];
                    if (rr == 0) {
                        uint32_t hi, lo; bsplit2(x0*SCALE, x1*SCALE, hi, lo);
                        g_qh[bhrow*64 + (dd>>1)] = hi;
                        g_ql[bhrow*64 + (dd>>1)] = lo;
                    } else if (rr == 1) {
                        uint32_t hi, lo; bsplit2(x0, x1, hi, lo);
                        g_kh[bhrow*64 + (dd>>1)] = hi;
                        g_kl[bhrow*64 + (dd>>1)] = lo;
                    } else {
                        *(float2*)&g_v[bhrow*EE + dd] = make_float2(x0, x1);
                    }
                }
            }
        }
    }
}

// ---------------- fused flash attention (32-key tiles, 2 CTAs/SM) ----------------
#define QP 68   // pitch for [row][d-pair] Q/K tiles
#define VP 20   // pitch for [d][key-pair] V tiles
#define KT 32
#define NKT (SEQ/KT)   // 16

#define OFF_QH 0
#define OFF_QL (OFF_QH + 128*QP)
#define OFF_KH (OFF_QL + 128*QP)
#define OFF_KL (OFF_KH + KT*QP)
#define OFF_VH (OFF_KL + KT*QP)
#define OFF_VL (OFF_VH + 128*VP)
#define OFF_WS (OFF_VL + 128*VP)
#define FLASH_WORDS (OFF_WS + KT)   // 26912 words = 107648 B

__global__ __launch_bounds__(256, 2)
void flash_kernel() {
    extern __shared__ uint32_t smx[];
    uint32_t* Qh = smx + OFF_QH;
    uint32_t* Ql = smx + OFF_QL;
    uint32_t* Kh = smx + OFF_KH;
    uint32_t* Kl = smx + OFF_KL;
    uint32_t* Vh = smx + OFF_VH;
    uint32_t* Vl = smx + OFF_VL;
    float*    ws = (float*)(smx + OFF_WS);

    int qt = blockIdx.x, bh = blockIdx.y;
    int b = bh >> 3, h = bh & 7;
    int tid = threadIdx.x;
    int lane = tid & 31;
    int wid = tid >> 5;
    int g = lane >> 2, tg = lane & 3;

    // Q tile: copy pre-split planes (128 rows x 64 words per plane)
    const uint32_t* Qgh = g_qh + ((size_t)bh*SEQ + qt*128)*64;
    const uint32_t* Qgl = g_ql + ((size_t)bh*SEQ + qt*128)*64;
    #pragma unroll
    for (int i = 0; i < 8; i++) {
        int c = i*256 + tid;               // 0..2047
        int row = c >> 4, q = (c & 15)*4;
        *(uint4*)&Qh[row*QP + q] = *(const uint4*)&Qgh[row*64 + q];
        *(uint4*)&Ql[row*QP + q] = *(const uint4*)&Qgl[row*64 + q];
    }

    int rowg = qt*128 + wid*16 + g;
    bool mq0 = g_w[b*SEQ + rowg]     > 0.f;
    bool mq1 = g_w[b*SEQ + rowg + 8] > 0.f;

    float m_run[2] = {-9.0e15f, -9.0e15f};
    float l_run[2] = {0.f, 0.f};
    float o[16][4];
    #pragma unroll
    for (int dt = 0; dt < 16; dt++)
        #pragma unroll
        for (int c = 0; c < 4; c++) o[dt][c] = 0.f;

    const uint32_t* Vbh = g_vth + (size_t)bh*EE*256;
    const uint32_t* Vbl = g_vtl + (size_t)bh*EE*256;

    for (int kt = 0; kt < NKT; kt++) {
        __syncthreads();
        if (tid < KT) ws[tid] = g_w[b*SEQ + kt*KT + tid];
        // K tile: 32 rows x 64 words per plane (FIXED full-footprint copy)
        {
            const uint32_t* Kgh = g_kh + ((size_t)bh*SEQ + kt*KT)*64;
            const uint32_t* Kgl = g_kl + ((size_t)bh*SEQ + kt*KT)*64;
            #pragma unroll
            for (int i = 0; i < 2; i++) {
                int c = i*256 + tid;       // 0..511
                int row = c >> 4, q = (c & 15)*4;
                *(uint4*)&Kh[row*QP + q] = *(const uint4*)&Kgh[row*64 + q];
                *(uint4*)&Kl[row*QP + q] = *(const uint4*)&Kgl[row*64 + q];
            }
        }
        // V tile: 128 d-rows x 16 words per plane (pre-transposed, pre-split)
        #pragma unroll
        for (int i = 0; i < 2; i++) {
            int c = i*256 + tid;           // 0..511
            int dd = c >> 2, q = (c & 3)*4;
            *(uint4*)&Vh[dd*VP + q] = *(const uint4*)&Vbh[(size_t)dd*256 + kt*16 + q];
            *(uint4*)&Vl[dd*VP + q] = *(const uint4*)&Vbl[(size_t)dd*256 + kt*16 + q];
        }
        __syncthreads();

        // ---- S = Q @ K^T (warp: 16 rows x 32 keys) ----
        float s[4][4];
        #pragma unroll
        for (int nt=0; nt<4; nt++)
            #pragma unroll
            for (int c=0; c<4; c++) s[nt][c] = 0.f;

        int m0 = wid*16 + g;
        #pragma unroll
        for (int ks = 0; ks < 8; ks++) {
            int kb = ks*8 + tg;
            uint32_t ah[4], al[4];
            ah[0] = Qh[m0*QP + kb];       al[0] = Ql[m0*QP + kb];
            ah[1] = Qh[(m0+8)*QP + kb];   al[1] = Ql[(m0+8)*QP + kb];
            ah[2] = Qh[m0*QP + kb+4];     al[2] = Ql[m0*QP + kb+4];
            ah[3] = Qh[(m0+8)*QP + kb+4]; al[3] = Ql[(m0+8)*QP + kb+4];
            #pragma unroll
            for (int nt = 0; nt < 4; nt++) {
                int n0 = nt*8 + g;
                uint32_t bh0 = Kh[n0*QP + kb], bh1 = Kh[n0*QP + kb+4];
                uint32_t bl0 = Kl[n0*QP + kb], bl1 = Kl[n0*QP + kb+4];
                mma_bf16(s[nt], ah, bh0, bh1);
                mma_bf16(s[nt], ah, bl0, bl1);
                mma_bf16(s[nt], al, bh0, bh1);
            }
        }

        // ---- mask + online softmax ----
        float tmax[2] = {-9.0e15f, -9.0e15f};
        #pragma unroll
        for (int nt = 0; nt < 4; nt++) {
            int col0 = nt*8 + 2*tg;
            #pragma unroll
            for (int c = 0; c < 4; c++) {
                bool mk = ws[col0 + (c & 1)] > 0.f;
                bool mr = (c < 2) ? mq0 : mq1;
                float v = (mk && mr) ? s[nt][c] : -9.0e15f;
                s[nt][c] = v;
                tmax[c >> 1] = fmaxf(tmax[c >> 1], v);
            }
        }
        #pragma unroll
        for (int off = 1; off <= 2; off <<= 1) {
            tmax[0] = fmaxf(tmax[0], __shfl_xor_sync(0xffffffffu, tmax[0], off));
            tmax[1] = fmaxf(tmax[1], __shfl_xor_sync(0xffffffffu, tmax[1], off));
        }
        float nm0 = fmaxf(m_run[0], tmax[0]);
        float nm1 = fmaxf(m_run[1], tmax[1]);
        float a0 = __expf(m_run[0] - nm0);
        float a1 = __expf(m_run[1] - nm1);
        float rs[2] = {0.f, 0.f};
        #pragma unroll
        for (int nt = 0; nt < 4; nt++) {
            int col0 = nt*8 + 2*tg;
            #pragma unroll
            for (int c = 0; c < 4; c++) {
                float nm = (c < 2) ? nm0 : nm1;
                float p = ws[col0 + (c & 1)] * __expf(s[nt][c] - nm);
                s[nt][c] = p;
                rs[c >> 1] += p;
            }
        }
        #pragma unroll
        for (int off = 1; off <= 2; off <<= 1) {
            rs[0] += __shfl_xor_sync(0xffffffffu, rs[0], off);
            rs[1] += __shfl_xor_sync(0xffffffffu, rs[1], off);
        }
        l_run[0] = a0*l_run[0] + rs[0];
        l_run[1] = a1*l_run[1] + rs[1];
        m_run[0] = nm0; m_run[1] = nm1;
        #pragma unroll
        for (int dt = 0; dt < 16; dt++) {
            o[dt][0] *= a0; o[dt][1] *= a0;
            o[dt][2] *= a1; o[dt][3] *= a1;
        }

        // ---- O += P @ V (2 k16 steps over 32 keys) ----
        #pragma unroll
        for (int j = 0; j < 2; j++) {
            uint32_t pah[4], pal[4];
            bsplit2(s[2*j  ][0], s[2*j  ][1], pah[0], pal[0]);
            bsplit2(s[2*j  ][2], s[2*j  ][3], pah[1], pal[1]);
            bsplit2(s[2*j+1][0], s[2*j+1][1], pah[2], pal[2]);
            bsplit2(s[2*j+1][2], s[2*j+1][3], pah[3], pal[3]);
            int kb = j*8 + tg;
            #pragma unroll
            for (int dt = 0; dt < 16; dt++) {
                int n0 = dt*8 + g;
                uint32_t vh0 = Vh[n0*VP + kb], vh1 = Vh[n0*VP + kb+4];
                uint32_t vl0 = Vl[n0*VP + kb], vl1 = Vl[n0*VP + kb+4];
                mma_bf16(o[dt], pah, vh0, vh1);
                mma_bf16(o[dt], pah, vl0, vl1);
                mma_bf16(o[dt], pal, vh0, vh1);
            }
        }
    }

    // ---- normalize + store split vals planes ----
    float inv0 = 1.f / l_run[0];
    float inv1 = 1.f / l_run[1];
    size_t r0 = (size_t)(b*SEQ) + qt*128 + wid*16 + g;
    size_t r1 = r0 + 8;
    #pragma unroll
    for (int dt = 0; dt < 16; dt++) {
        int w = h*64 + dt*4 + tg;
        uint32_t hi, lo;
        bsplit2(o[dt][0]*inv0, o[dt][1]*inv0, hi, lo);
        g_valsh[r0*512 + w] = hi; g_valsl[r0*512 + w] = lo;
        bsplit2(o[dt][2]*inv1, o[dt][3]*inv1, hi, lo);
        g_valsh[r1*512 + w] = hi; g_valsl[r1*512 + w] = lo;
    }
}

// ---------------- final: weighted pool + LN + head ----------------
__global__ void pool_head_kernel(const float* __restrict__ ln2_g,
                                 const float* __restrict__ ln2_b,
                                 const float* __restrict__ head_W,
                                 const float* __restrict__ head_b,
                                 float* __restrict__ out) {
    __shared__ float sm[4];
    int b = blockIdx.x, e = threadIdx.x;
    const float* xb  = g_x     + (size_t)b*SEQ*EE;
    const float* xib = g_xinit + (size_t)b*SEQ*EE;
    float s = 0.f;
    for (int n = 0; n < SEQ; n++)
        s = fmaf(g_w[b*SEQ + n], xb[n*EE + e] + xib[n*EE + e], s);
    float m = blkSum128(s, sm) * (1.f/EE);
    float d = s - m;
    float var = blkSum128(d*d, sm) * (1.f/EE);
    float p = d * rsqrtf(var + 1e-5f) * ln2_g[e] + ln2_b[e];
    float dot = blkSum128(p * head_W[e], sm);
    if (e == 0) out[b] = dot + head_b[0];
}

// ---------------- host launch ----------------
#define GEMM_SMEM (2*4*PL*4)

extern "C" void kernel_launch(void* const* d_in, const int* in_sizes, int n_in,
                              void* d_out, int out_size) {
    (void)in_sizes; (void)n_in; (void)out_size;
    const float* str_fea   = (const float*)d_in[0];
    const int*   comp_fea  = (const int*)  d_in[1];
    const float* atom_table= (const float*)d_in[3];
    const float* comp_W    = (const float*)d_in[4];
    const float* comp_b    = (const float*)d_in[5];
    const float* pdd_W     = (const float*)d_in[6];
    const float* pdd_b     = (const float*)d_in[7];
    const float* enc_ln_g  = (const float*)d_in[8];
    const float* enc_ln_b  = (const float*)d_in[9];
    const float* qkv_W     = (const float*)d_in[10];
    const float* qkv_b     = (const float*)d_in[11];
    const float* o_W       = (const float*)d_in[12];
    const float* o_b       = (const float*)d_in[13];
    const float* out_W     = (const float*)d_in[14];
    const float* out_b     = (const float*)d_in[15];
    const float* ffn_W     = (const float*)d_in[16];
    const float* ffn_b     = (const float*)d_in[17];
    const float* ln2_g     = (const float*)d_in[18];
    const float* ln2_b     = (const float*)d_in[19];
    const float* head_W    = (const float*)d_in[20];
    const float* head_b    = (const float*)d_in[21];
    float* out = (float*)d_out;

    void* p;
    cudaGetSymbolAddress(&p, g_x);      float* px    = (float*)p;
    cudaGetSymbolAddress(&p, g_out1);   float* pout1 = (float*)p;
    cudaGetSymbolAddress(&p, g_out2);   float* pout2 = (float*)p;
    cudaGetSymbolAddress(&p, g_xnh);    uint32_t* pxnh = (uint32_t*)p;
    cudaGetSymbolAddress(&p, g_xnl);    uint32_t* pxnl = (uint32_t*)p;
    cudaGetSymbolAddress(&p, g_valsh);  uint32_t* pvalsh = (uint32_t*)p;
    cudaGetSymbolAddress(&p, g_valsl);  uint32_t* pvalsl = (uint32_t*)p;
    cudaGetSymbolAddress(&p, g_oh);     uint32_t* poh = (uint32_t*)p;
    cudaGetSymbolAddress(&p, g_ol);     uint32_t* pol = (uint32_t*)p;
    cudaGetSymbolAddress(&p, g_Wqkvh);  uint32_t* pWqkvh = (uint32_t*)p;
    cudaGetSymbolAddress(&p, g_Wqkvl);  uint32_t* pWqkvl = (uint32_t*)p;
    cudaGetSymbolAddress(&p, g_Woh);    uint32_t* pWoh = (uint32_t*)p;
    cudaGetSymbolAddress(&p, g_Wol);    uint32_t* pWol = (uint32_t*)p;
    cudaGetSymbolAddress(&p, g_Wouth);  uint32_t* pWouth = (uint32_t*)p;
    cudaGetSymbolAddress(&p, g_Woutl);  uint32_t* pWoutl = (uint32_t*)p;
    cudaGetSymbolAddress(&p, g_Wffnh);  uint32_t* pWffnh = (uint32_t*)p;
    cudaGetSymbolAddress(&p, g_Wffnl);  uint32_t* pWffnl = (uint32_t*)p;

    cudaFuncSetAttribute(flash_kernel,
        cudaFuncAttributeMaxDynamicSharedMemorySize, FLASH_WORDS * 4);
    cudaFuncSetAttribute(gemm_kernel<EPI_BIAS_PACK>,
        cudaFuncAttributeMaxDynamicSharedMemorySize, GEMM_SMEM);
    cudaFuncSetAttribute(gemm_kernel<EPI_BIAS_ADD>,
        cudaFuncAttributeMaxDynamicSharedMemorySize, GEMM_SMEM);
    cudaFuncSetAttribute(gemm_kernel<EPI_MISH>,
        cudaFuncAttributeMaxDynamicSharedMemorySize, GEMM_SMEM);
    cudaFuncSetAttribute(gemm_kernel<EPI_QKV>,
        cudaFuncAttributeMaxDynamicSharedMemorySize, GEMM_SMEM);

    // ---- pre-split all weights (gridDim.y = layer) ----
    split_weights_kernel<<<dim3((3072*64 + 255)/256, LL), 256>>>(
        qkv_W, pWqkvh, pWqkvl, EE, 3*EHH);
    split_weights_kernel<<<dim3((1024*512 + 255)/256, LL), 256>>>(
        o_W, pWoh, pWol, EHH, EHH);
    split_weights_kernel<<<dim3((128*512 + 255)/256, LL), 256>>>(
        out_W, pWouth, pWoutl, EHH, EE);
    split_weights_kernel<<<dim3((128*64 + 255)/256, LL), 256>>>(
        ffn_W, pWffnh, pWffnl, EE, EE);

    embed_kernel<<<TOK, EE>>>(str_fea, comp_fea, atom_table,
                              comp_W, comp_b, pdd_W, pdd_b);

    for (int i = 0; i < LL; i++) {
        const float* g = enc_ln_g + i*EE;
        const float* bta = enc_ln_b + i*EE;

        // xn = LN(x) -> packed planes
        ln_kernel<1><<<TOK/4, 128>>>(px, nullptr, g, bta, nullptr, pxnh, pxnl);

        // qkv projection -> packed q (scaled) / packed k / float v
        gemm_kernel<EPI_QKV><<<dim3(3*EHH/BN, TOK/BM), 256, GEMM_SMEM>>>(
            pxnh, pxnl, 64,
            pWqkvh + (size_t)i*3072*64, pWqkvl + (size_t)i*3072*64, 64,
            nullptr, 0, nullptr, nullptr, 0, EE,
            qkv_b + (size_t)i*3*EHH, nullptr);

        // V -> transposed packed planes
        transpose_v_kernel<<<dim3(SEQ/64, BHH), 256>>>();

        // fused attention -> packed vals planes
        flash_kernel<<<dim3(4, BHH), 256, FLASH_WORDS*4>>>();

        // o = vals @ o_W + o_b -> packed o planes
        gemm_kernel<EPI_BIAS_PACK><<<dim3(EHH/BN, TOK/BM), 256, GEMM_SMEM>>>(
            pvalsh, pvalsl, 512,
            pWoh + (size_t)i*1024*512, pWol + (size_t)i*1024*512, 512,
            nullptr, 0, poh, pol, 512, EHH,
            o_b + (size_t)i*EHH, nullptr);

        // out1 = x + o @ out_W + out_b (float)
        gemm_kernel<EPI_BIAS_ADD><<<dim3(EE/BN, TOK/BM), 256, GEMM_SMEM>>>(
            poh, pol, 512,
            pWouth + (size_t)i*128*512, pWoutl + (size_t)i*128*512, 512,
            pout1, EE, nullptr, nullptr, 0, EHH,
            out_b + (size_t)i*EE, px);

        // xn = LN(out1) -> packed planes
        ln_kernel<1><<<TOK/4, 128>>>(pout1, nullptr, g, bta, nullptr, pxnh, pxnl);

        // out2 = mish(xn @ ffn_W + ffn_b) (float)
        gemm_kernel<EPI_MISH><<<dim3(EE/BN, TOK/BM), 256, GEMM_SMEM>>>(
            pxnh, pxnl, 64,
            pWffnh + (size_t)i*128*64, pWffnl + (size_t)i*128*64, 64,
            pout2, EE, nullptr, nullptr, 0, EE,
            ffn_b + (size_t)i*EE, nullptr);

        // x = LN(out1 + out2) (float)
        ln_kernel<0><<<TOK/4, 128>>>(pout1, pout2, g, bta, px, nullptr, nullptr);
    }

    pool_head_kernel<<<Bb, EE>>>(ln2_g, ln2_b, head_W, head_b, out);
}

// round 14
// speedup vs baseline: 3.8705x; 1.3757x over previous
#include <cuda_runtime.h>
#include <cuda_bf16.h>
#include <math.h>
#include <stdint.h>

// ---------------- problem constants ----------------
#define Bb   32
#define SEQ  512
#define EE   128
#define HH   8
#define EHH  1024
#define LL   3
#define TOK  (Bb*SEQ)      // 16384 tokens
#define BHH  (Bb*HH)       // 256 (b,h) pairs
#define KF   101
#define ADIM 200
#define SCALE 0.08838834764831845f

// ---------------- device scratch ----------------
__device__ float g_x    [(size_t)TOK*EE];
__device__ float g_xinit[(size_t)TOK*EE];
__device__ float g_out1 [(size_t)TOK*EE];
__device__ float g_out2 [(size_t)TOK*EE];
__device__ float g_w    [TOK];
__device__ float g_v    [(size_t)BHH*SEQ*EE];

// packed bf16 hi/lo activation planes ([rows][K/2] uint32 words)
__device__ uint32_t g_xnh [(size_t)TOK*64],  g_xnl [(size_t)TOK*64];
__device__ uint32_t g_qh  [(size_t)BHH*SEQ*64], g_ql[(size_t)BHH*SEQ*64];
__device__ uint32_t g_kh  [(size_t)BHH*SEQ*64], g_kl[(size_t)BHH*SEQ*64];
__device__ uint32_t g_vth [(size_t)BHH*EE*256], g_vtl[(size_t)BHH*EE*256]; // V^T packed [bh][d][tokpair]
__device__ uint32_t g_valsh[(size_t)TOK*512], g_valsl[(size_t)TOK*512];

// packed weight planes ([N][K/2], per layer)
__device__ uint32_t g_Wqkvh[(size_t)LL*3072*64],  g_Wqkvl[(size_t)LL*3072*64];
__device__ uint32_t g_Wffnh[(size_t)LL*128*64],   g_Wffnl[(size_t)LL*128*64];

// combined o_W@out_W weight: fp32 staging + packed planes + combined bias
__device__ float    g_Wc  [(size_t)LL*EHH*EE];
__device__ float    g_bc  [(size_t)LL*EE];
__device__ uint32_t g_Wch [(size_t)LL*128*512], g_Wcl[(size_t)LL*128*512];

// ---------------- helpers ----------------
__device__ __forceinline__ float blkSum128(float v, float* sm) {
    #pragma unroll
    for (int o = 16; o > 0; o >>= 1) v += __shfl_xor_sync(0xffffffffu, v, o);
    int w = threadIdx.x >> 5;
    if ((threadIdx.x & 31) == 0) sm[w] = v;
    __syncthreads();
    float r = sm[0] + sm[1] + sm[2] + sm[3];
    __syncthreads();
    return r;
}

__device__ __forceinline__ void bsplit2(float x, float y, uint32_t& hi, uint32_t& lo) {
    __nv_bfloat16 xh = __float2bfloat16(x);
    __nv_bfloat16 yh = __float2bfloat16(y);
    float xr = x - __bfloat162float(xh);
    float yr = y - __bfloat162float(yh);
    __nv_bfloat162 h2 = __halves2bfloat162(xh, yh);
    __nv_bfloat162 l2 = __halves2bfloat162(__float2bfloat16(xr), __float2bfloat16(yr));
    hi = *reinterpret_cast<uint32_t*>(&h2);
    lo = *reinterpret_cast<uint32_t*>(&l2);
}

__device__ __forceinline__ void mma_bf16(float* d, const uint32_t* a,
                                         uint32_t b0, uint32_t b1) {
    asm volatile(
        "mma.sync.aligned.m16n8k16.row.col.f32.bf16.bf16.f32 "
        "{%0,%1,%2,%3}, {%4,%5,%6,%7}, {%8,%9}, {%0,%1,%2,%3};\n"
        : "+f"(d[0]), "+f"(d[1]), "+f"(d[2]), "+f"(d[3])
        : "r"(a[0]), "r"(a[1]), "r"(a[2]), "r"(a[3]), "r"(b0), "r"(b1));
}

__device__ __forceinline__ void cp16(uint32_t* sdst, const uint32_t* gsrc) {
    uint32_t s = (uint32_t)__cvta_generic_to_shared(sdst);
    asm volatile("cp.async.ca.shared.global [%0], [%1], 16;" :: "r"(s), "l"(gsrc));
}

// ---------------- weight split: W[K][N] float -> planes [N][K/2]; y = layer ----------------
__global__ void split_weights_kernel(const float* __restrict__ W,
                                     uint32_t* __restrict__ oh,
                                     uint32_t* __restrict__ ol,
                                     int K, int N) {
    int kw = K >> 1;
    size_t lw = (size_t)N*kw;
    int L = blockIdx.y;
    W  += (size_t)L*K*N;
    oh += (size_t)L*lw;
    ol += (size_t)L*lw;
    int idx = blockIdx.x*256 + threadIdx.x;
    if (idx >= N*kw) return;
    int n = idx % N, kp = idx / N;
    float w0 = W[(size_t)(2*kp)*N + n];
    float w1 = W[(size_t)(2*kp+1)*N + n];
    uint32_t hi, lo; bsplit2(w0, w1, hi, lo);
    oh[(size_t)n*kw + kp] = hi;
    ol[(size_t)n*kw + kp] = lo;
}

// ---------------- combined weight precompute: Wc = o_W @ out_W (fp32) ----------------
// grid (EHH, LL), 128 threads; block computes row k of Wc for layer L.
__global__ void combine_w_kernel(const float* __restrict__ oW,
                                 const float* __restrict__ outW) {
    int L = blockIdx.y;
    int k = blockIdx.x;
    int n = threadIdx.x;
    const float* ow = oW  + (size_t)L*EHH*EHH + (size_t)k*EHH;
    const float* uw = outW + (size_t)L*EHH*EE;
    __shared__ float so[EHH];
    for (int j = threadIdx.x; j < EHH; j += EE) so[j] = ow[j];
    __syncthreads();
    float acc = 0.f;
    #pragma unroll 8
    for (int j = 0; j < EHH; j++) acc = fmaf(so[j], uw[(size_t)j*EE + n], acc);
    g_Wc[(size_t)L*EHH*EE + (size_t)k*EE + n] = acc;
}

// bc = o_b @ out_W + out_b ; grid LL, 128 threads
__global__ void combine_b_kernel(const float* __restrict__ ob,
                                 const float* __restrict__ outW,
                                 const float* __restrict__ outb) {
    int L = blockIdx.x;
    int n = threadIdx.x;
    const float* uw = outW + (size_t)L*EHH*EE;
    const float* obl = ob + (size_t)L*EHH;
    float acc = outb[(size_t)L*EE + n];
    #pragma unroll 8
    for (int j = 0; j < EHH; j++) acc = fmaf(obl[j], uw[(size_t)j*EE + n], acc);
    g_bc[(size_t)L*EE + n] = acc;
}

// ---------------- embed ----------------
__global__ void embed_kernel(const float* __restrict__ str_fea,
                             const int*   __restrict__ comp_fea,
                             const float* __restrict__ atom_table,
                             const float* __restrict__ comp_W,
                             const float* __restrict__ comp_b,
                             const float* __restrict__ pdd_W,
                             const float* __restrict__ pdd_b) {
    int t = blockIdx.x;
    int e = threadIdx.x;
    __shared__ float sa[ADIM];
    __shared__ float ss[KF-1];
    const float* sf = str_fea + (size_t)t*KF;
    int idx = comp_fea[t];
    const float* at = atom_table + (size_t)idx*ADIM;
    for (int j = e; j < ADIM; j += EE) sa[j] = at[j];
    for (int j = e; j < KF-1; j += EE) ss[j] = sf[1+j];
    if (e == 0) g_w[t] = sf[0];
    __syncthreads();
    float acc = comp_b[e] + pdd_b[e];
    #pragma unroll 4
    for (int a = 0; a < ADIM; a++) acc = fmaf(sa[a], comp_W[a*EE + e], acc);
    #pragma unroll 4
    for (int j = 0; j < KF-1; j++) acc = fmaf(ss[j], pdd_W[j*EE + e], acc);
    g_x[(size_t)t*EE + e]     = acc;
    g_xinit[(size_t)t*EE + e] = acc;
}

// ---------------- warp-per-token layernorm; PACKED=1 -> bf16 hi/lo planes ----------------
template<int PACKED>
__global__ void ln_kernel(const float* __restrict__ src1,
                          const float* __restrict__ src2,
                          const float* __restrict__ gam,
                          const float* __restrict__ bet,
                          float* __restrict__ dstf,
                          uint32_t* __restrict__ dsth,
                          uint32_t* __restrict__ dstl) {
    int warp = threadIdx.x >> 5, lane = threadIdx.x & 31;
    int t = blockIdx.x*4 + warp;
    size_t off = (size_t)t*EE + lane*4;
    float4 v = *(const float4*)&src1[off];
    if (src2) {
        const float4 u = *(const float4*)&src2[off];
        v.x += u.x; v.y += u.y; v.z += u.z; v.w += u.w;
    }
    float s = v.x + v.y + v.z + v.w;
    #pragma unroll
    for (int o = 16; o > 0; o >>= 1) s += __shfl_xor_sync(0xffffffffu, s, o);
    float m = s * (1.f/EE);
    float dx = v.x - m, dy = v.y - m, dz = v.z - m, dw = v.w - m;
    float q = dx*dx + dy*dy + dz*dz + dw*dw;
    #pragma unroll
    for (int o = 16; o > 0; o >>= 1) q += __shfl_xor_sync(0xffffffffu, q, o);
    float rstd = rsqrtf(q * (1.f/EE) + 1e-5f);
    const float4 gv = *(const float4*)&gam[lane*4];
    const float4 bv = *(const float4*)&bet[lane*4];
    float r0 = dx*rstd*gv.x + bv.x;
    float r1 = dy*rstd*gv.y + bv.y;
    float r2 = dz*rstd*gv.z + bv.z;
    float r3 = dw*rstd*gv.w + bv.w;
    if (PACKED) {
        uint32_t h0, l0, h1, l1;
        bsplit2(r0, r1, h0, l0);
        bsplit2(r2, r3, h1, l1);
        *(uint2*)&dsth[(size_t)t*64 + lane*2] = make_uint2(h0, h1);
        *(uint2*)&dstl[(size_t)t*64 + lane*2] = make_uint2(l0, l1);
    } else {
        *(float4*)&dstf[off] = make_float4(r0, r1, r2, r3);
    }
}

// ---------------- V transpose+split: g_v [bh][tok][d] -> packed [bh][d][tokpair] ----------------
__global__ void transpose_v_kernel() {
    __shared__ float sv[64][129];
    int bh = blockIdx.y, t0 = blockIdx.x*64;
    int tid = threadIdx.x;
    const float* Vg = g_v + ((size_t)bh*SEQ + t0)*EE;
    #pragma unroll
    for (int i = 0; i < 8; i++) {
        int c = i*256 + tid;               // 0..2047 float4s
        int tok = c >> 5, q = (c & 31)*4;
        const float4 f = *(const float4*)&Vg[(size_t)tok*EE + q];
        sv[tok][q]   = f.x; sv[tok][q+1] = f.y;
        sv[tok][q+2] = f.z; sv[tok][q+3] = f.w;
    }
    __syncthreads();
    uint32_t* oh = g_vth + (size_t)bh*EE*256 + (t0 >> 1);
    uint32_t* ol = g_vtl + (size_t)bh*EE*256 + (t0 >> 1);
    #pragma unroll
    for (int i = 0; i < 16; i++) {
        int widx = i*256 + tid;            // 0..4095
        int d = widx >> 5, tp = widx & 31;
        uint32_t hi, lo;
        bsplit2(sv[2*tp][d], sv[2*tp+1][d], hi, lo);
        oh[(size_t)d*256 + tp] = hi;
        ol[(size_t)d*256 + tp] = lo;
    }
}

// ---------------- pre-split bf16 GEMM (3-mma), cp.async double-buffered ----------------
#define BM 128
#define BN 128
#define GP 20   // smem row pitch in words
#define PL 2560 // plane size: 128*GP

enum { EPI_BIAS_ADD=1, EPI_MISH=2, EPI_QKV=3 };

template<int EPI>
__global__ __launch_bounds__(256, 2)
void gemm_kernel(const uint32_t* __restrict__ Ah_g, const uint32_t* __restrict__ Al_g, int lda,
                 const uint32_t* __restrict__ Bh_g, const uint32_t* __restrict__ Bl_g, int ldb,
                 float* __restrict__ C, int ldc,
                 int K,
                 const float* __restrict__ bias,
                 const float* __restrict__ addend) {
    extern __shared__ uint32_t smx[];
    int bm = blockIdx.y * BM, bn = blockIdx.x * BN;

    int tid  = threadIdx.x;
    int lane = tid & 31;
    int wid  = tid >> 5;
    int warpM = wid & 3;
    int warpN = wid >> 2;
    int g  = lane >> 2;
    int tg = lane & 3;

    float d[2][8][4];
    #pragma unroll
    for (int mt=0; mt<2; mt++)
        #pragma unroll
        for (int nt=0; nt<8; nt++)
            #pragma unroll
            for (int c=0; c<4; c++) d[mt][nt][c] = 0.f;

    int nIter = K >> 5;

    {
        uint32_t* s = smx;
        #pragma unroll
        for (int i = 0; i < 2; i++) {
            int c = i*256 + tid;
            int row = c >> 2, q = (c & 3)*4;
            cp16(&s[0*PL + row*GP + q], Ah_g + (size_t)(bm+row)*lda + q);
            cp16(&s[1*PL + row*GP + q], Al_g + (size_t)(bm+row)*lda + q);
            cp16(&s[2*PL + row*GP + q], Bh_g + (size_t)(bn+row)*ldb + q);
            cp16(&s[3*PL + row*GP + q], Bl_g + (size_t)(bn+row)*ldb + q);
        }
    }
    asm volatile("cp.async.commit_group;" ::: "memory");

    for (int it = 0; it < nIter; it++) {
        asm volatile("cp.async.wait_group 0;" ::: "memory");
        __syncthreads();
        if (it + 1 < nIter) {
            uint32_t* s = smx + ((it+1)&1)*4*PL;
            int kw = (it+1)*16;
            #pragma unroll
            for (int i = 0; i < 2; i++) {
                int c = i*256 + tid;
                int row = c >> 2, q = (c & 3)*4;
                cp16(&s[0*PL + row*GP + q], Ah_g + (size_t)(bm+row)*lda + kw + q);
                cp16(&s[1*PL + row*GP + q], Al_g + (size_t)(bm+row)*lda + kw + q);
                cp16(&s[2*PL + row*GP + q], Bh_g + (size_t)(bn+row)*ldb + kw + q);
                cp16(&s[3*PL + row*GP + q], Bl_g + (size_t)(bn+row)*ldb + kw + q);
            }
            asm volatile("cp.async.commit_group;" ::: "memory");
        }

        const uint32_t* Ah = smx + (it&1)*4*PL;
        const uint32_t* Al = Ah + PL;
        const uint32_t* Bh = Al + PL;
        const uint32_t* Bl = Bh + PL;

        #pragma unroll
        for (int js = 0; js < 2; js++) {
            int kb = js*8 + tg;
            uint32_t ah[2][4], al[2][4];
            #pragma unroll
            for (int mt = 0; mt < 2; mt++) {
                int m0 = warpM*32 + mt*16 + g;
                ah[mt][0] = Ah[m0*GP + kb];       al[mt][0] = Al[m0*GP + kb];
                ah[mt][1] = Ah[(m0+8)*GP + kb];   al[mt][1] = Al[(m0+8)*GP + kb];
                ah[mt][2] = Ah[m0*GP + kb+4];     al[mt][2] = Al[m0*GP + kb+4];
                ah[mt][3] = Ah[(m0+8)*GP + kb+4]; al[mt][3] = Al[(m0+8)*GP + kb+4];
            }
            #pragma unroll
            for (int nt = 0; nt < 8; nt++) {
                int n0 = warpN*64 + nt*8 + g;
                uint32_t bh0 = Bh[n0*GP + kb], bh1 = Bh[n0*GP + kb+4];
                uint32_t bl0 = Bl[n0*GP + kb], bl1 = Bl[n0*GP + kb+4];
                #pragma unroll
                for (int mt = 0; mt < 2; mt++) {
                    mma_bf16(d[mt][nt], ah[mt], bh0, bh1);
                    mma_bf16(d[mt][nt], ah[mt], bl0, bl1);
                    mma_bf16(d[mt][nt], al[mt], bh0, bh1);
                }
            }
        }
    }

    #pragma unroll
    for (int mt = 0; mt < 2; mt++) {
        #pragma unroll
        for (int nt = 0; nt < 8; nt++) {
            #pragma unroll
            for (int half = 0; half < 2; half++) {
                int m = bm + warpM*32 + mt*16 + g + half*8;
                int n = bn + warpN*64 + nt*8 + 2*tg;
                float v0 = d[mt][nt][half*2 + 0];
                float v1 = d[mt][nt][half*2 + 1];
                if (EPI == EPI_BIAS_ADD) {
                    const float2 ad = *(const float2*)&addend[(size_t)m*ldc + n];
                    float2 r = make_float2(v0 + bias[n] + ad.x, v1 + bias[n+1] + ad.y);
                    *(float2*)&C[(size_t)m*ldc + n] = r;
                } else if (EPI == EPI_MISH) {
                    float x0 = v0 + bias[n],  x1 = v1 + bias[n+1];
                    float s0 = (x0 > 20.f) ? x0 : log1pf(expf(x0));
                    float s1 = (x1 > 20.f) ? x1 : log1pf(expf(x1));
                    float2 r = make_float2(x0 * tanhf(s0), x1 * tanhf(s1));
                    *(float2*)&C[(size_t)m*ldc + n] = r;
                } else { // EPI_QKV
                    int b = m >> 9, tok = m & 511;
                    int hh = n / 384, rem = n % 384;
                    int rr = rem >> 7, dd = rem & 127;
                    size_t bhrow = ((size_t)(b*HH + hh)*SEQ + tok);
                    float x0 = v0 + bias[n], x1 = v1 + bias[n+1];
                    if (rr == 0) {
                        uint32_t hi, lo; bsplit2(x0*SCALE, x1*SCALE, hi, lo);
                        g_qh[bhrow*64 + (dd>>1)] = hi;
                        g_ql[bhrow*64 + (dd>>1)] = lo;
                    } else if (rr == 1) {
                        uint32_t hi, lo; bsplit2(x0, x1, hi, lo);
                        g_kh[bhrow*64 + (dd>>1)] = hi;
                        g_kl[bhrow*64 + (dd>>1)] = lo;
                    } else {
                        *(float2*)&g_v[bhrow*EE + dd] = make_float2(x0, x1);
                    }
                }
            }
        }
    }
}

// ---------------- fused flash attention (32-key tiles, 2 CTAs/SM) ----------------
#define QP 68   // pitch for [row][d-pair] Q/K tiles
#define VP 20   // pitch for [d][key-pair] V tiles
#define KT 32
#define NKT (SEQ/KT)   // 16

#define OFF_QH 0
#define OFF_QL (OFF_QH + 128*QP)
#define OFF_KH (OFF_QL + 128*QP)
#define OFF_KL (OFF_KH + KT*QP)
#define OFF_VH (OFF_KL + KT*QP)
#define OFF_VL (OFF_VH + 128*VP)
#define OFF_WS (OFF_VL + 128*VP)
#define FLASH_WORDS (OFF_WS + KT)   // 26912 words = 107648 B

__global__ __launch_bounds__(256, 2)
void flash_kernel() {
    extern __shared__ uint32_t smx[];
    uint32_t* Qh = smx + OFF_QH;
    uint32_t* Ql = smx + OFF_QL;
    uint32_t* Kh = smx + OFF_KH;
    uint32_t* Kl = smx + OFF_KL;
    uint32_t* Vh = smx + OFF_VH;
    uint32_t* Vl = smx + OFF_VL;
    float*    ws = (float*)(smx + OFF_WS);

    int qt = blockIdx.x, bh = blockIdx.y;
    int b = bh >> 3, h = bh & 7;
    int tid = threadIdx.x;
    int lane = tid & 31;
    int wid = tid >> 5;
    int g = lane >> 2, tg = lane & 3;

    // Q tile: copy pre-split planes (128 rows x 64 words per plane)
    const uint32_t* Qgh = g_qh + ((size_t)bh*SEQ + qt*128)*64;
    const uint32_t* Qgl = g_ql + ((size_t)bh*SEQ + qt*128)*64;
    #pragma unroll
    for (int i = 0; i < 8; i++) {
        int c = i*256 + tid;               // 0..2047
        int row = c >> 4, q = (c & 15)*4;
        *(uint4*)&Qh[row*QP + q] = *(const uint4*)&Qgh[row*64 + q];
        *(uint4*)&Ql[row*QP + q] = *(const uint4*)&Qgl[row*64 + q];
    }

    int rowg = qt*128 + wid*16 + g;
    bool mq0 = g_w[b*SEQ + rowg]     > 0.f;
    bool mq1 = g_w[b*SEQ + rowg + 8] > 0.f;

    float m_run[2] = {-9.0e15f, -9.0e15f};
    float l_run[2] = {0.f, 0.f};
    float o[16][4];
    #pragma unroll
    for (int dt = 0; dt < 16; dt++)
        #pragma unroll
        for (int c = 0; c < 4; c++) o[dt][c] = 0.f;

    const uint32_t* Vbh = g_vth + (size_t)bh*EE*256;
    const uint32_t* Vbl = g_vtl + (size_t)bh*EE*256;

    for (int kt = 0; kt < NKT; kt++) {
        __syncthreads();
        if (tid < KT) ws[tid] = g_w[b*SEQ + kt*KT + tid];
        // K tile: 32 rows x 64 words per plane
        {
            const uint32_t* Kgh = g_kh + ((size_t)bh*SEQ + kt*KT)*64;
            const uint32_t* Kgl = g_kl + ((size_t)bh*SEQ + kt*KT)*64;
            #pragma unroll
            for (int i = 0; i < 2; i++) {
                int c = i*256 + tid;       // 0..511
                int row = c >> 4, q = (c & 15)*4;
                *(uint4*)&Kh[row*QP + q] = *(const uint4*)&Kgh[row*64 + q];
                *(uint4*)&Kl[row*QP + q] = *(const uint4*)&Kgl[row*64 + q];
            }
        }
        // V tile: 128 d-rows x 16 words per plane (pre-transposed, pre-split)
        #pragma unroll
        for (int i = 0; i < 2; i++) {
            int c = i*256 + tid;           // 0..511
            int dd = c >> 2, q = (c & 3)*4;
            *(uint4*)&Vh[dd*VP + q] = *(const uint4*)&Vbh[(size_t)dd*256 + kt*16 + q];
            *(uint4*)&Vl[dd*VP + q] = *(const uint4*)&Vbl[(size_t)dd*256 + kt*16 + q];
        }
        __syncthreads();

        // ---- S = Q @ K^T (warp: 16 rows x 32 keys) ----
        float s[4][4];
        #pragma unroll
        for (int nt=0; nt<4; nt++)
            #pragma unroll
            for (int c=0; c<4; c++) s[nt][c] = 0.f;

        int m0 = wid*16 + g;
        #pragma unroll
        for (int ks = 0; ks < 8; ks++) {
            int kb = ks*8 + tg;
            uint32_t ah[4], al[4];
            ah[0] = Qh[m0*QP + kb];       al[0] = Ql[m0*QP + kb];
            ah[1] = Qh[(m0+8)*QP + kb];   al[1] = Ql[(m0+8)*QP + kb];
            ah[2] = Qh[m0*QP + kb+4];     al[2] = Ql[m0*QP + kb+4];
            ah[3] = Qh[(m0+8)*QP + kb+4]; al[3] = Ql[(m0+8)*QP + kb+4];
            #pragma unroll
            for (int nt = 0; nt < 4; nt++) {
                int n0 = nt*8 + g;
                uint32_t bh0 = Kh[n0*QP + kb], bh1 = Kh[n0*QP + kb+4];
                uint32_t bl0 = Kl[n0*QP + kb], bl1 = Kl[n0*QP + kb+4];
                mma_bf16(s[nt], ah, bh0, bh1);
                mma_bf16(s[nt], ah, bl0, bl1);
                mma_bf16(s[nt], al, bh0, bh1);
            }
        }

        // ---- mask + online softmax ----
        float tmax[2] = {-9.0e15f, -9.0e15f};
        #pragma unroll
        for (int nt = 0; nt < 4; nt++) {
            int col0 = nt*8 + 2*tg;
            #pragma unroll
            for (int c = 0; c < 4; c++) {
                bool mk = ws[col0 + (c & 1)] > 0.f;
                bool mr = (c < 2) ? mq0 : mq1;
                float v = (mk && mr) ? s[nt][c] : -9.0e15f;
                s[nt][c] = v;
                tmax[c >> 1] = fmaxf(tmax[c >> 1], v);
            }
        }
        #pragma unroll
        for (int off = 1; off <= 2; off <<= 1) {
            tmax[0] = fmaxf(tmax[0], __shfl_xor_sync(0xffffffffu, tmax[0], off));
            tmax[1] = fmaxf(tmax[1], __shfl_xor_sync(0xffffffffu, tmax[1], off));
        }
        float nm0 = fmaxf(m_run[0], tmax[0]);
        float nm1 = fmaxf(m_run[1], tmax[1]);
        float a0 = __expf(m_run[0] - nm0);
        float a1 = __expf(m_run[1] - nm1);
        float rs[2] = {0.f, 0.f};
        #pragma unroll
        for (int nt = 0; nt < 4; nt++) {
            int col0 = nt*8 + 2*tg;
            #pragma unroll
            for (int c = 0; c < 4; c++) {
                float nm = (c < 2) ? nm0 : nm1;
                float p = ws[col0 + (c & 1)] * __expf(s[nt][c] - nm);
                s[nt][c] = p;
                rs[c >> 1] += p;
            }
        }
        #pragma unroll
        for (int off = 1; off <= 2; off <<= 1) {
            rs[0] += __shfl_xor_sync(0xffffffffu, rs[0], off);
            rs[1] += __shfl_xor_sync(0xffffffffu, rs[1], off);
        }
        l_run[0] = a0*l_run[0] + rs[0];
        l_run[1] = a1*l_run[1] + rs[1];
        m_run[0] = nm0; m_run[1] = nm1;
        #pragma unroll
        for (int dt = 0; dt < 16; dt++) {
            o[dt][0] *= a0; o[dt][1] *= a0;
            o[dt][2] *= a1; o[dt][3] *= a1;
        }

        // ---- O += P @ V (2 k16 steps over 32 keys) ----
        #pragma unroll
        for (int j = 0; j < 2; j++) {
            uint32_t pah[4], pal[4];
            bsplit2(s[2*j  ][0], s[2*j  ][1], pah[0], pal[0]);
            bsplit2(s[2*j  ][2], s[2*j  ][3], pah[1], pal[1]);
            bsplit2(s[2*j+1][0], s[2*j+1][1], pah[2], pal[2]);
            bsplit2(s[2*j+1][2], s[2*j+1][3], pah[3], pal[3]);
            int kb = j*8 + tg;
            #pragma unroll
            for (int dt = 0; dt < 16; dt++) {
                int n0 = dt*8 + g;
                uint32_t vh0 = Vh[n0*VP + kb], vh1 = Vh[n0*VP + kb+4];
                uint32_t vl0 = Vl[n0*VP + kb], vl1 = Vl[n0*VP + kb+4];
                mma_bf16(o[dt], pah, vh0, vh1);
                mma_bf16(o[dt], pah, vl0, vl1);
                mma_bf16(o[dt], pal, vh0, vh1);
            }
        }
    }

    // ---- normalize + store split vals planes ----
    float inv0 = 1.f / l_run[0];
    float inv1 = 1.f / l_run[1];
    size_t r0 = (size_t)(b*SEQ) + qt*128 + wid*16 + g;
    size_t r1 = r0 + 8;
    #pragma unroll
    for (int dt = 0; dt < 16; dt++) {
        int w = h*64 + dt*4 + tg;
        uint32_t hi, lo;
        bsplit2(o[dt][0]*inv0, o[dt][1]*inv0, hi, lo);
        g_valsh[r0*512 + w] = hi; g_valsl[r0*512 + w] = lo;
        bsplit2(o[dt][2]*inv1, o[dt][3]*inv1, hi, lo);
        g_valsh[r1*512 + w] = hi; g_valsl[r1*512 + w] = lo;
    }
}

// ---------------- final: weighted pool + LN + head ----------------
__global__ void pool_head_kernel(const float* __restrict__ ln2_g,
                                 const float* __restrict__ ln2_b,
                                 const float* __restrict__ head_W,
                                 const float* __restrict__ head_b,
                                 float* __restrict__ out) {
    __shared__ float sm[4];
    int b = blockIdx.x, e = threadIdx.x;
    const float* xb  = g_x     + (size_t)b*SEQ*EE;
    const float* xib = g_xinit + (size_t)b*SEQ*EE;
    float s = 0.f;
    for (int n = 0; n < SEQ; n++)
        s = fmaf(g_w[b*SEQ + n], xb[n*EE + e] + xib[n*EE + e], s);
    float m = blkSum128(s, sm) * (1.f/EE);
    float d = s - m;
    float var = blkSum128(d*d, sm) * (1.f/EE);
    float p = d * rsqrtf(var + 1e-5f) * ln2_g[e] + ln2_b[e];
    float dot = blkSum128(p * head_W[e], sm);
    if (e == 0) out[b] = dot + head_b[0];
}

// ---------------- host launch ----------------
#define GEMM_SMEM (2*4*PL*4)

extern "C" void kernel_launch(void* const* d_in, const int* in_sizes, int n_in,
                              void* d_out, int out_size) {
    (void)in_sizes; (void)n_in; (void)out_size;
    const float* str_fea   = (const float*)d_in[0];
    const int*   comp_fea  = (const int*)  d_in[1];
    const float* atom_table= (const float*)d_in[3];
    const float* comp_W    = (const float*)d_in[4];
    const float* comp_b    = (const float*)d_in[5];
    const float* pdd_W     = (const float*)d_in[6];
    const float* pdd_b     = (const float*)d_in[7];
    const float* enc_ln_g  = (const float*)d_in[8];
    const float* enc_ln_b  = (const float*)d_in[9];
    const float* qkv_W     = (const float*)d_in[10];
    const float* qkv_b     = (const float*)d_in[11];
    const float* o_W       = (const float*)d_in[12];
    const float* o_b       = (const float*)d_in[13];
    const float* out_W     = (const float*)d_in[14];
    const float* out_b     = (const float*)d_in[15];
    const float* ffn_W     = (const float*)d_in[16];
    const float* ffn_b     = (const float*)d_in[17];
    const float* ln2_g     = (const float*)d_in[18];
    const float* ln2_b     = (const float*)d_in[19];
    const float* head_W    = (const float*)d_in[20];
    const float* head_b    = (const float*)d_in[21];
    float* out = (float*)d_out;

    void* p;
    cudaGetSymbolAddress(&p, g_x);      float* px    = (float*)p;
    cudaGetSymbolAddress(&p, g_out1);   float* pout1 = (float*)p;
    cudaGetSymbolAddress(&p, g_out2);   float* pout2 = (float*)p;
    cudaGetSymbolAddress(&p, g_xnh);    uint32_t* pxnh = (uint32_t*)p;
    cudaGetSymbolAddress(&p, g_xnl);    uint32_t* pxnl = (uint32_t*)p;
    cudaGetSymbolAddress(&p, g_valsh);  uint32_t* pvalsh = (uint32_t*)p;
    cudaGetSymbolAddress(&p, g_valsl);  uint32_t* pvalsl = (uint32_t*)p;
    cudaGetSymbolAddress(&p, g_Wqkvh);  uint32_t* pWqkvh = (uint32_t*)p;
    cudaGetSymbolAddress(&p, g_Wqkvl);  uint32_t* pWqkvl = (uint32_t*)p;
    cudaGetSymbolAddress(&p, g_Wffnh);  uint32_t* pWffnh = (uint32_t*)p;
    cudaGetSymbolAddress(&p, g_Wffnl);  uint32_t* pWffnl = (uint32_t*)p;
    cudaGetSymbolAddress(&p, g_Wc);     float* pWc = (float*)p;
    cudaGetSymbolAddress(&p, g_bc);     float* pbc = (float*)p;
    cudaGetSymbolAddress(&p, g_Wch);    uint32_t* pWch = (uint32_t*)p;
    cudaGetSymbolAddress(&p, g_Wcl);    uint32_t* pWcl = (uint32_t*)p;

    cudaFuncSetAttribute(flash_kernel,
        cudaFuncAttributeMaxDynamicSharedMemorySize, FLASH_WORDS * 4);
    cudaFuncSetAttribute(gemm_kernel<EPI_BIAS_ADD>,
        cudaFuncAttributeMaxDynamicSharedMemorySize, GEMM_SMEM);
    cudaFuncSetAttribute(gemm_kernel<EPI_MISH>,
        cudaFuncAttributeMaxDynamicSharedMemorySize, GEMM_SMEM);
    cudaFuncSetAttribute(gemm_kernel<EPI_QKV>,
        cudaFuncAttributeMaxDynamicSharedMemorySize, GEMM_SMEM);

    // ---- precompute combined o_W@out_W weight + bias, then split ----
    combine_w_kernel<<<dim3(EHH, LL), EE>>>(o_W, out_W);
    combine_b_kernel<<<LL, EE>>>(o_b, out_W, out_b);
    split_weights_kernel<<<dim3((128*512 + 255)/256, LL), 256>>>(
        pWc, pWch, pWcl, EHH, EE);

    // ---- pre-split remaining weights ----
    split_weights_kernel<<<dim3((3072*64 + 255)/256, LL), 256>>>(
        qkv_W, pWqkvh, pWqkvl, EE, 3*EHH);
    split_weights_kernel<<<dim3((128*64 + 255)/256, LL), 256>>>(
        ffn_W, pWffnh, pWffnl, EE, EE);

    embed_kernel<<<TOK, EE>>>(str_fea, comp_fea, atom_table,
                              comp_W, comp_b, pdd_W, pdd_b);

    for (int i = 0; i < LL; i++) {
        const float* g = enc_ln_g + i*EE;
        const float* bta = enc_ln_b + i*EE;

        // xn = LN(x) -> packed planes
        ln_kernel<1><<<TOK/4, 128>>>(px, nullptr, g, bta, nullptr, pxnh, pxnl);

        // qkv projection -> packed q (scaled) / packed k / float v
        gemm_kernel<EPI_QKV><<<dim3(3*EHH/BN, TOK/BM), 256, GEMM_SMEM>>>(
            pxnh, pxnl, 64,
            pWqkvh + (size_t)i*3072*64, pWqkvl + (size_t)i*3072*64, 64,
            nullptr, 0, EE,
            qkv_b + (size_t)i*3*EHH, nullptr);

        // V -> transposed packed planes
        transpose_v_kernel<<<dim3(SEQ/64, BHH), 256>>>();

        // fused attention -> packed vals planes
        flash_kernel<<<dim3(4, BHH), 256, FLASH_WORDS*4>>>();

        // out1 = x + vals @ (o_W@out_W) + (o_b@out_W + out_b)   [fused projection]
        gemm_kernel<EPI_BIAS_ADD><<<dim3(EE/BN, TOK/BM), 256, GEMM_SMEM>>>(
            pvalsh, pvalsl, 512,
            pWch + (size_t)i*128*512, pWcl + (size_t)i*128*512, 512,
            pout1, EE, EHH,
            pbc + (size_t)i*EE, px);

        // xn = LN(out1) -> packed planes
        ln_kernel<1><<<TOK/4, 128>>>(pout1, nullptr, g, bta, nullptr, pxnh, pxnl);

        // out2 = mish(xn @ ffn_W + ffn_b) (float)
        gemm_kernel<EPI_MISH><<<dim3(EE/BN, TOK/BM), 256, GEMM_SMEM>>>(
            pxnh, pxnl, 64,
            pWffnh + (size_t)i*128*64, pWffnl + (size_t)i*128*64, 64,
            pout2, EE, EE,
            ffn_b + (size_t)i*EE, nullptr);

        // x = LN(out1 + out2) (float)
        ln_kernel<0><<<TOK/4, 128>>>(pout1, pout2, g, bta, px, nullptr, nullptr);
    }

    pool_head_kernel<<<Bb, EE>>>(ln2_g, ln2_b, head_W, head_b, out);
}